// round 1
// baseline (speedup 1.0000x reference)
#include <cuda_runtime.h>
#include <math.h>
#include <stdint.h>

// Problem constants
// B=2, N=2048, C=1024, H=16, D=64
#define NB 2
#define NN 2048
#define NC 1024
#define NH 16
#define ND 64
#define NTOK (NB * NN)          // 4096

// ---------------- scratch (device globals; no allocation allowed) -----------
__device__ float g_qkv[NTOK * 3 * NC];      // [tok][3C]      50.3 MB
__device__ float g_q[NB * NH * NN * ND];    // head-major     16.8 MB
__device__ float g_k[NB * NH * NN * ND];
__device__ float g_v[NB * NH * NN * ND];
__device__ float g_att[NTOK * NC];          // attention out, token-major

// =============================================================================
// SGEMM: C[M,N] = A[M,K] * B[N,K]^T (+bias). 128x128 tile, BK=8, 8x8/thread.
// Requires M%128==0, N%128==0, K%8==0 (true for all our shapes).
// =============================================================================
template <bool HAS_BIAS>
__global__ __launch_bounds__(256) void sgemm_nt(
    const float* __restrict__ A, const float* __restrict__ Bm,
    const float* __restrict__ bias, float* __restrict__ C,
    int M, int Nc, int K)
{
    __shared__ float As[8][128];
    __shared__ float Bs[8][128];

    const int t  = threadIdx.x;
    const int tx = t & 15, ty = t >> 4;
    const int tx4 = tx * 4, ty4 = ty * 4;

    const float* Ab = A  + (size_t)(blockIdx.y * 128) * K;
    const float* Bb = Bm + (size_t)(blockIdx.x * 128) * K;

    const int lrow = t >> 1;         // 0..127
    const int lcol = (t & 1) * 4;    // 0 or 4

    float acc[8][8];
#pragma unroll
    for (int i = 0; i < 8; i++)
#pragma unroll
        for (int j = 0; j < 8; j++) acc[i][j] = 0.0f;

    for (int k0 = 0; k0 < K; k0 += 8) {
        float4 av = *(const float4*)(Ab + (size_t)lrow * K + k0 + lcol);
        float4 bv = *(const float4*)(Bb + (size_t)lrow * K + k0 + lcol);
        __syncthreads();
        As[lcol + 0][lrow] = av.x; As[lcol + 1][lrow] = av.y;
        As[lcol + 2][lrow] = av.z; As[lcol + 3][lrow] = av.w;
        Bs[lcol + 0][lrow] = bv.x; Bs[lcol + 1][lrow] = bv.y;
        Bs[lcol + 2][lrow] = bv.z; Bs[lcol + 3][lrow] = bv.w;
        __syncthreads();

#pragma unroll
        for (int kk = 0; kk < 8; kk++) {
            float a[8], b[8];
            *(float4*)&a[0] = *(const float4*)&As[kk][ty4];
            *(float4*)&a[4] = *(const float4*)&As[kk][64 + ty4];
            *(float4*)&b[0] = *(const float4*)&Bs[kk][tx4];
            *(float4*)&b[4] = *(const float4*)&Bs[kk][64 + tx4];
#pragma unroll
            for (int i = 0; i < 8; i++)
#pragma unroll
                for (int j = 0; j < 8; j++)
                    acc[i][j] = fmaf(a[i], b[j], acc[i][j]);
        }
    }

#pragma unroll
    for (int i = 0; i < 8; i++) {
        int m = blockIdx.y * 128 + ((i < 4) ? (ty4 + i) : (64 + ty4 + i - 4));
#pragma unroll
        for (int jg = 0; jg < 2; jg++) {
            int nb = blockIdx.x * 128 + jg * 64 + tx4;
            float4 v = make_float4(acc[i][jg * 4 + 0], acc[i][jg * 4 + 1],
                                   acc[i][jg * 4 + 2], acc[i][jg * 4 + 3]);
            if (HAS_BIAS) {
                v.x += bias[nb + 0]; v.y += bias[nb + 1];
                v.z += bias[nb + 2]; v.w += bias[nb + 3];
            }
            *(float4*)(C + (size_t)m * Nc + nb) = v;
        }
    }
}

// =============================================================================
// Normalize q,k over full C=1024 (x / max(||x||,eps)) * (1/sqrt(D)),
// split into head-major [B,H,N,D] layout. v is just relaid out.
// One block per token; thread t owns the float4 at channel t*4.
// =============================================================================
__global__ __launch_bounds__(256) void norm_split_kernel(
    const float* __restrict__ qkv,
    float* __restrict__ q, float* __restrict__ k, float* __restrict__ v)
{
    const int tok = blockIdx.x;
    const int b = tok >> 11;          // /2048
    const int n = tok & 2047;
    const float* row = qkv + (size_t)tok * (3 * NC);
    const int t = threadIdx.x;

    float4 qv = *(const float4*)(row + t * 4);
    float4 kv = *(const float4*)(row + NC + t * 4);
    float4 vv = *(const float4*)(row + 2 * NC + t * 4);

    float sq = qv.x * qv.x + qv.y * qv.y + qv.z * qv.z + qv.w * qv.w;
    float sk = kv.x * kv.x + kv.y * kv.y + kv.z * kv.z + kv.w * kv.w;

#pragma unroll
    for (int m = 16; m > 0; m >>= 1) {
        sq += __shfl_xor_sync(0xffffffffu, sq, m);
        sk += __shfl_xor_sync(0xffffffffu, sk, m);
    }
    __shared__ float red[2][8];
    const int warp = t >> 5, lane = t & 31;
    if (lane == 0) { red[0][warp] = sq; red[1][warp] = sk; }
    __syncthreads();
    float sqt = 0.f, skt = 0.f;
#pragma unroll
    for (int w = 0; w < 8; w++) { sqt += red[0][w]; skt += red[1][w]; }

    const float qs = 0.125f / fmaxf(sqrtf(sqt), 1e-12f);   // 1/sqrt(64)=0.125
    const float ks = 0.125f / fmaxf(sqrtf(skt), 1e-12f);

    const int h = t >> 4;            // channel group t*4 -> head (t*4)/64
    const int d = (t & 15) * 4;
    const size_t off = ((size_t)(b * NH + h) * NN + n) * ND + d;

    *(float4*)&q[off] = make_float4(qv.x * qs, qv.y * qs, qv.z * qs, qv.w * qs);
    *(float4*)&k[off] = make_float4(kv.x * ks, kv.y * ks, kv.z * ks, kv.w * ks);
    *(float4*)&v[off] = vv;
}

// =============================================================================
// Attention. |logit| <= 1/64 -> no max subtraction needed (softmax invariant).
// Block: 128 query rows for one (b,h); loop over 64-key tiles of 2048 keys.
// 256 threads (16x16); each thread: 8 q-rows x 4 cols register tile.
// Shared: Qts[d][q] 64x128, Kts[d][key] 64x64, Vs[key][d] 64x(64 pad 68),
//         Ps[q][key] 128x(64 pad 68). Total 101376 bytes (dynamic).
// =============================================================================
#define ATTN_SMEM_FLOATS (64 * 128 + 64 * 64 + 64 * 68 + 128 * 68)
#define ATTN_SMEM_BYTES  (ATTN_SMEM_FLOATS * 4)

__global__ __launch_bounds__(256) void attn_kernel(
    const float* __restrict__ q, const float* __restrict__ k,
    const float* __restrict__ v, const float* __restrict__ temp,
    float* __restrict__ att)
{
    extern __shared__ float smem[];
    float* Qts = smem;                        // [64][128]
    float* Kts = Qts + 64 * 128;              // [64][64]
    float* Vs  = Kts + 64 * 64;               // [64][68]
    float* Ps  = Vs  + 64 * 68;               // [128][68]

    const int t  = threadIdx.x;
    const int tx = t & 15, ty = t >> 4;
    const int tx4 = tx * 4, ty4 = ty * 4;
    const int qtile = blockIdx.x;             // 0..15
    const int bh = blockIdx.y;                // 0..31
    const int b = bh >> 4, h = bh & 15;

    const float invT = 1.0f / temp[h];
    const float* qg = q + ((size_t)bh * NN + qtile * 128) * ND;
    const float* kg = k + (size_t)bh * NN * ND;
    const float* vg = v + (size_t)bh * NN * ND;

    // Load Q tile transposed (d-major), fold in 1/temperature
    for (int idx = t; idx < 128 * 16; idx += 256) {
        int qrow = idx & 127;
        int dg = idx >> 7;                    // 0..15
        float4 val = *(const float4*)(qg + (size_t)qrow * ND + dg * 4);
        Qts[(dg * 4 + 0) * 128 + qrow] = val.x * invT;
        Qts[(dg * 4 + 1) * 128 + qrow] = val.y * invT;
        Qts[(dg * 4 + 2) * 128 + qrow] = val.z * invT;
        Qts[(dg * 4 + 3) * 128 + qrow] = val.w * invT;
    }

    float o[8][4];
    float l[8];
#pragma unroll
    for (int i = 0; i < 8; i++) {
        l[i] = 0.0f;
#pragma unroll
        for (int j = 0; j < 4; j++) o[i][j] = 0.0f;
    }

    int rowoff[8];
#pragma unroll
    for (int i = 0; i < 8; i++)
        rowoff[i] = ((i < 4) ? (ty4 + i) : (64 + ty4 + i - 4)) * 68;

    for (int kv0 = 0; kv0 < NN; kv0 += 64) {
        __syncthreads();   // protect Vs/Kts/Ps from previous iteration's readers
        // Load K (transposed to d-major) and V tiles
        for (int idx = t; idx < 64 * 16; idx += 256) {
            int key = idx & 63;
            int dg = idx >> 6;                // 0..15
            float4 kvv = *(const float4*)(kg + (size_t)(kv0 + key) * ND + dg * 4);
            Kts[(dg * 4 + 0) * 64 + key] = kvv.x;
            Kts[(dg * 4 + 1) * 64 + key] = kvv.y;
            Kts[(dg * 4 + 2) * 64 + key] = kvv.z;
            Kts[(dg * 4 + 3) * 64 + key] = kvv.w;
            float4 vvv = *(const float4*)(vg + (size_t)(kv0 + key) * ND + dg * 4);
            *(float4*)&Vs[key * 68 + dg * 4] = vvv;
        }
        __syncthreads();

        // S = Q @ K^T for this tile (128 x 64), register tile 8x4
        float s[8][4];
#pragma unroll
        for (int i = 0; i < 8; i++)
#pragma unroll
            for (int j = 0; j < 4; j++) s[i][j] = 0.0f;

#pragma unroll 8
        for (int d = 0; d < 64; ++d) {
            float4 a0 = *(const float4*)&Qts[d * 128 + ty4];
            float4 a1 = *(const float4*)&Qts[d * 128 + 64 + ty4];
            float4 bv = *(const float4*)&Kts[d * 64 + tx4];
            float aa[8] = {a0.x, a0.y, a0.z, a0.w, a1.x, a1.y, a1.z, a1.w};
#pragma unroll
            for (int i = 0; i < 8; i++) {
                s[i][0] = fmaf(aa[i], bv.x, s[i][0]);
                s[i][1] = fmaf(aa[i], bv.y, s[i][1]);
                s[i][2] = fmaf(aa[i], bv.z, s[i][2]);
                s[i][3] = fmaf(aa[i], bv.w, s[i][3]);
            }
        }

        // P = exp(S); accumulate row sums; stash P (q-major, padded)
#pragma unroll
        for (int i = 0; i < 8; i++) {
            float e0 = __expf(s[i][0]);
            float e1 = __expf(s[i][1]);
            float e2 = __expf(s[i][2]);
            float e3 = __expf(s[i][3]);
            l[i] += (e0 + e1) + (e2 + e3);
            *(float4*)&Ps[rowoff[i] + tx4] = make_float4(e0, e1, e2, e3);
        }
        __syncthreads();

        // O += P @ V  (128 x 64)
#pragma unroll 4
        for (int kk = 0; kk < 64; ++kk) {
            float4 bv = *(const float4*)&Vs[kk * 68 + tx4];
#pragma unroll
            for (int i = 0; i < 8; i++) {
                float a = Ps[rowoff[i] + kk];
                o[i][0] = fmaf(a, bv.x, o[i][0]);
                o[i][1] = fmaf(a, bv.y, o[i][1]);
                o[i][2] = fmaf(a, bv.z, o[i][2]);
                o[i][3] = fmaf(a, bv.w, o[i][3]);
            }
        }
    }

    // Reduce row sums across the 16 tx lanes (xor bits 0..3 stay in-group)
#pragma unroll
    for (int i = 0; i < 8; i++) {
        float li = l[i];
        li += __shfl_xor_sync(0xffffffffu, li, 1);
        li += __shfl_xor_sync(0xffffffffu, li, 2);
        li += __shfl_xor_sync(0xffffffffu, li, 4);
        li += __shfl_xor_sync(0xffffffffu, li, 8);
        l[i] = li;
    }

    // Normalize, write token-major [tok][C] for the projection GEMM
#pragma unroll
    for (int i = 0; i < 8; i++) {
        float inv = 1.0f / l[i];
        int r = (i < 4) ? (ty4 + i) : (64 + ty4 + i - 4);
        int qrow = qtile * 128 + r;
        size_t off = ((size_t)(b * NN + qrow)) * NC + h * ND + tx4;
        *(float4*)&att[off] = make_float4(o[i][0] * inv, o[i][1] * inv,
                                          o[i][2] * inv, o[i][3] * inv);
    }
}

// =============================================================================
// Launch
// =============================================================================
extern "C" void kernel_launch(void* const* d_in, const int* in_sizes, int n_in,
                              void* d_out, int out_size)
{
    (void)in_sizes; (void)n_in; (void)out_size;
    const float* x      = (const float*)d_in[0];   // [2,2048,1024]
    const float* qkv_w  = (const float*)d_in[1];   // [3072,1024]
    const float* temp   = (const float*)d_in[2];   // [16,1,1]
    const float* proj_w = (const float*)d_in[3];   // [1024,1024]
    const float* proj_b = (const float*)d_in[4];   // [1024]
    float* out = (float*)d_out;                    // [2,2048,1024]

    float *p_qkv, *p_q, *p_k, *p_v, *p_att;
    cudaGetSymbolAddress((void**)&p_qkv, g_qkv);
    cudaGetSymbolAddress((void**)&p_q,   g_q);
    cudaGetSymbolAddress((void**)&p_k,   g_k);
    cudaGetSymbolAddress((void**)&p_v,   g_v);
    cudaGetSymbolAddress((void**)&p_att, g_att);

    cudaFuncSetAttribute(attn_kernel,
                         cudaFuncAttributeMaxDynamicSharedMemorySize,
                         ATTN_SMEM_BYTES);

    // 1) QKV GEMM: [4096,3072] = x[4096,1024] @ qkv_w^T
    sgemm_nt<false><<<dim3(3 * NC / 128, NTOK / 128), 256>>>(
        x, qkv_w, nullptr, p_qkv, NTOK, 3 * NC, NC);

    // 2) L2-normalize q,k over full C; split heads
    norm_split_kernel<<<NTOK, 256>>>(p_qkv, p_q, p_k, p_v);

    // 3) Attention per (b,h), 128-query tiles
    attn_kernel<<<dim3(NN / 128, NB * NH), 256, ATTN_SMEM_BYTES>>>(
        p_q, p_k, p_v, temp, p_att);

    // 4) Projection: out[4096,1024] = att @ proj_w^T + proj_b
    sgemm_nt<true><<<dim3(NC / 128, NTOK / 128), 256>>>(
        p_att, proj_w, proj_b, out, NTOK, NC, NC);
}

// round 2
// speedup vs baseline: 2.4947x; 2.4947x over previous
#include <cuda_runtime.h>
#include <math.h>
#include <stdint.h>

// B=2, N=2048, C=1024, H=16, D=64
#define NB 2
#define NN 2048
#define NC 1024
#define NH 16
#define ND 64
#define NTOK (NB * NN)

// ---------------- scratch ----------------
__device__ float g_qkv[NTOK * 3 * NC];
__device__ float g_q[NTOK * NC];
__device__ float g_k[NTOK * NC];
__device__ float g_v[NTOK * NC];
__device__ float g_att[NTOK * NC];

// ---------------- PTX helpers ----------------
__device__ __forceinline__ uint32_t f2tf(float f) {
    uint32_t u;
    asm("cvt.rna.tf32.f32 %0, %1;" : "=r"(u) : "f"(f));
    return u;
}
__device__ __forceinline__ void ldm_x4(uint32_t& r0, uint32_t& r1,
                                       uint32_t& r2, uint32_t& r3, uint32_t addr) {
    asm volatile("ldmatrix.sync.aligned.m8n8.x4.shared.b16 {%0,%1,%2,%3}, [%4];"
                 : "=r"(r0), "=r"(r1), "=r"(r2), "=r"(r3) : "r"(addr));
}
__device__ __forceinline__ void mma_tf32(float* c, const uint32_t* a,
                                         uint32_t b0, uint32_t b1) {
    asm volatile(
        "mma.sync.aligned.m16n8k8.row.col.f32.tf32.tf32.f32 "
        "{%0,%1,%2,%3}, {%4,%5,%6,%7}, {%8,%9}, {%0,%1,%2,%3};"
        : "+f"(c[0]), "+f"(c[1]), "+f"(c[2]), "+f"(c[3])
        : "r"(a[0]), "r"(a[1]), "r"(a[2]), "r"(a[3]), "r"(b0), "r"(b1));
}
__device__ __forceinline__ uint32_t smem_u32(const void* p) {
    return (uint32_t)__cvta_generic_to_shared(p);
}

// =============================================================================
// TF32 GEMM: C[M,N] = A[M,K] * B[N,K]^T (+bias)
// Block 128x128, Ktile=16, 8 warps (2 in M x 4 in N), warp tile 64x32.
// SMEM rows padded to 20 floats (5x16B atoms, odd -> conflict-free ldmatrix).
// =============================================================================
#define GK   16
#define GLDS 20

template <bool HAS_BIAS>
__global__ __launch_bounds__(256) void gemm_tf32(
    const float* __restrict__ A, const float* __restrict__ Bm,
    const float* __restrict__ bias, float* __restrict__ C,
    int M, int Nc, int K)
{
    __shared__ float As[128 * GLDS];
    __shared__ float Bs[128 * GLDS];

    const int t = threadIdx.x;
    const int w = t >> 5, lane = t & 31;
    const int wm = w >> 2, wn = w & 3;       // warp coords: 2 x 4

    const float* Ab = A  + (size_t)(blockIdx.y * 128) * K;
    const float* Bb = Bm + (size_t)(blockIdx.x * 128) * K;

    // global->smem: row = t>>1 (128 rows), two float4 atoms per thread
    const int lrow = t >> 1;
    const int lat  = (t & 1) * 2;

    // ldmatrix per-lane offsets
    const int a_row = (lane & 7) + ((lane >> 3) & 1) * 8;   // A-fragment row in 16-row tile
    const int a_col = ((lane >> 4) << 2);                   // 0 or 4
    const int b_row = (lane & 7) + ((lane >> 4) << 3);      // B-fragment row in 16-row tile
    const int b_col = ((lane >> 3) & 1) * 4;                // 0 or 4

    const uint32_t as_base = smem_u32(As);
    const uint32_t bs_base = smem_u32(Bs);

    float acc[4][4][4];
#pragma unroll
    for (int mi = 0; mi < 4; mi++)
#pragma unroll
        for (int ni = 0; ni < 4; ni++)
#pragma unroll
            for (int j = 0; j < 4; j++) acc[mi][ni][j] = 0.0f;

    for (int k0 = 0; k0 < K; k0 += GK) {
        // global loads (2 float4 per matrix per thread)
        float4 av0 = *(const float4*)(Ab + (size_t)lrow * K + k0 + (lat + 0) * 4);
        float4 av1 = *(const float4*)(Ab + (size_t)lrow * K + k0 + (lat + 1) * 4);
        float4 bv0 = *(const float4*)(Bb + (size_t)lrow * K + k0 + (lat + 0) * 4);
        float4 bv1 = *(const float4*)(Bb + (size_t)lrow * K + k0 + (lat + 1) * 4);

        __syncthreads();
        {
            uint32_t* ap = (uint32_t*)&As[lrow * GLDS + lat * 4];
            uint32_t* bp = (uint32_t*)&Bs[lrow * GLDS + lat * 4];
            ap[0] = f2tf(av0.x); ap[1] = f2tf(av0.y); ap[2] = f2tf(av0.z); ap[3] = f2tf(av0.w);
            ap[4] = f2tf(av1.x); ap[5] = f2tf(av1.y); ap[6] = f2tf(av1.z); ap[7] = f2tf(av1.w);
            bp[0] = f2tf(bv0.x); bp[1] = f2tf(bv0.y); bp[2] = f2tf(bv0.z); bp[3] = f2tf(bv0.w);
            bp[4] = f2tf(bv1.x); bp[5] = f2tf(bv1.y); bp[6] = f2tf(bv1.z); bp[7] = f2tf(bv1.w);
        }
        __syncthreads();

#pragma unroll
        for (int ks = 0; ks < 2; ks++) {
            const int kc = ks * 8;
            uint32_t a[4][4];
#pragma unroll
            for (int mi = 0; mi < 4; mi++) {
                uint32_t addr = as_base +
                    ((wm * 64 + mi * 16 + a_row) * GLDS + kc + a_col) * 4;
                ldm_x4(a[mi][0], a[mi][1], a[mi][2], a[mi][3], addr);
            }
            uint32_t b[2][4];
#pragma unroll
            for (int np = 0; np < 2; np++) {
                uint32_t addr = bs_base +
                    ((wn * 32 + np * 16 + b_row) * GLDS + kc + b_col) * 4;
                ldm_x4(b[np][0], b[np][1], b[np][2], b[np][3], addr);
            }
#pragma unroll
            for (int mi = 0; mi < 4; mi++)
#pragma unroll
                for (int ni = 0; ni < 4; ni++)
                    mma_tf32(acc[mi][ni], a[mi],
                             b[ni >> 1][(ni & 1) * 2], b[ni >> 1][(ni & 1) * 2 + 1]);
        }
    }

    // epilogue
    const int erow0 = blockIdx.y * 128 + wm * 64 + (lane >> 2);
    const int ecol0 = blockIdx.x * 128 + wn * 32 + (lane & 3) * 2;
#pragma unroll
    for (int mi = 0; mi < 4; mi++) {
#pragma unroll
        for (int ni = 0; ni < 4; ni++) {
            int r = erow0 + mi * 16;
            int c = ecol0 + ni * 8;
            float2 v01 = make_float2(acc[mi][ni][0], acc[mi][ni][1]);
            float2 v23 = make_float2(acc[mi][ni][2], acc[mi][ni][3]);
            if (HAS_BIAS) {
                float b0 = bias[c], b1 = bias[c + 1];
                v01.x += b0; v01.y += b1;
                v23.x += b0; v23.y += b1;
            }
            *(float2*)(C + (size_t)r * Nc + c)       = v01;
            *(float2*)(C + (size_t)(r + 8) * Nc + c) = v23;
        }
    }
}

// =============================================================================
// Normalize q,k over full C (x / max(||x||,eps)) * (1/sqrt(D)); head-split.
// =============================================================================
__global__ __launch_bounds__(256) void norm_split_kernel(
    const float* __restrict__ qkv,
    float* __restrict__ q, float* __restrict__ k, float* __restrict__ v)
{
    const int tok = blockIdx.x;
    const int b = tok >> 11;
    const int n = tok & 2047;
    const float* row = qkv + (size_t)tok * (3 * NC);
    const int t = threadIdx.x;

    float4 qv = *(const float4*)(row + t * 4);
    float4 kv = *(const float4*)(row + NC + t * 4);
    float4 vv = *(const float4*)(row + 2 * NC + t * 4);

    float sq = qv.x * qv.x + qv.y * qv.y + qv.z * qv.z + qv.w * qv.w;
    float sk = kv.x * kv.x + kv.y * kv.y + kv.z * kv.z + kv.w * kv.w;
#pragma unroll
    for (int m = 16; m > 0; m >>= 1) {
        sq += __shfl_xor_sync(0xffffffffu, sq, m);
        sk += __shfl_xor_sync(0xffffffffu, sk, m);
    }
    __shared__ float red[2][8];
    const int warp = t >> 5, lane = t & 31;
    if (lane == 0) { red[0][warp] = sq; red[1][warp] = sk; }
    __syncthreads();
    float sqt = 0.f, skt = 0.f;
#pragma unroll
    for (int w = 0; w < 8; w++) { sqt += red[0][w]; skt += red[1][w]; }

    const float qs = 0.125f / fmaxf(sqrtf(sqt), 1e-12f);
    const float ks = 0.125f / fmaxf(sqrtf(skt), 1e-12f);

    const int h = t >> 4;
    const int d = (t & 15) * 4;
    const size_t off = ((size_t)(b * NH + h) * NN + n) * ND + d;
    *(float4*)&q[off] = make_float4(qv.x * qs, qv.y * qs, qv.z * qs, qv.w * qs);
    *(float4*)&k[off] = make_float4(kv.x * ks, kv.y * ks, kv.z * ks, kv.w * ks);
    *(float4*)&v[off] = vv;
}

// =============================================================================
// Attention (TF32 mma). |logit| <= 1/64 -> softmax without max subtraction.
// Block: 128 q-rows of one (b,h); 8 warps, warp w owns rows [16w,16w+16).
// 64-key tiles. SMEM strides = 68 floats (17 atoms, conflict-free ldmatrix).
//   Qs[128][68] (tf32, invT folded), Ks[64][68] (tf32),
//   Vs[64][68] d-major transposed (tf32), Ps[128][68] (tf32).
// =============================================================================
#define ALDS 68
#define ATTN_SMEM_FLOATS (128 * ALDS + 64 * ALDS + 64 * ALDS + 128 * ALDS)
#define ATTN_SMEM_BYTES  (ATTN_SMEM_FLOATS * 4)

__global__ __launch_bounds__(256) void attn_kernel(
    const float* __restrict__ q, const float* __restrict__ k,
    const float* __restrict__ v, const float* __restrict__ temp,
    float* __restrict__ att)
{
    extern __shared__ float smem[];
    float* Qs = smem;                      // [128][68]
    float* Ks = Qs + 128 * ALDS;           // [64][68]
    float* Vs = Ks + 64 * ALDS;            // [64][68], [d][key]
    float* Ps = Vs + 64 * ALDS;            // [128][68]

    const int t = threadIdx.x;
    const int w = t >> 5, lane = t & 31;
    const int qtile = blockIdx.x;
    const int bh = blockIdx.y;
    const int b = bh >> 4, h = bh & 15;

    const float invT = 1.0f / temp[h];
    const float* qg = q + ((size_t)bh * NN + qtile * 128) * ND;
    const float* kg = k + (size_t)bh * NN * ND;
    const float* vg = v + (size_t)bh * NN * ND;

    const uint32_t qs_base = smem_u32(Qs);
    const uint32_t ks_base = smem_u32(Ks);
    const uint32_t vs_base = smem_u32(Vs);
    const uint32_t ps_base = smem_u32(Ps);

    // ldmatrix lane offsets
    const int a_row = (lane & 7) + ((lane >> 3) & 1) * 8;
    const int a_col = ((lane >> 4) << 2);
    const int b_row = (lane & 7) + ((lane >> 4) << 3);
    const int b_col = ((lane >> 3) & 1) * 4;

    // ---- load Q tile (fold invT, round to tf32) ----
    {
        const int row = t >> 1;
        const int at0 = (t & 1) * 8;
        uint32_t* qp = (uint32_t*)&Qs[row * ALDS + at0 * 4];
        const float* src = qg + (size_t)row * ND + at0 * 4;
#pragma unroll
        for (int j = 0; j < 8; j++) {
            float4 val = *(const float4*)(src + j * 4);
            qp[j * 4 + 0] = f2tf(val.x * invT);
            qp[j * 4 + 1] = f2tf(val.y * invT);
            qp[j * 4 + 2] = f2tf(val.z * invT);
            qp[j * 4 + 3] = f2tf(val.w * invT);
        }
    }

    float o[8][4];
#pragma unroll
    for (int ni = 0; ni < 8; ni++)
#pragma unroll
        for (int j = 0; j < 4; j++) o[ni][j] = 0.0f;
    float lsum0 = 0.0f, lsum1 = 0.0f;

    const int prow0 = w * 16 + (lane >> 2);          // P/O row (first half)
    const int pcol0 = (lane & 3) * 2;

    for (int kv0 = 0; kv0 < NN; kv0 += 64) {
        __syncthreads();
        // ---- load K and V tiles ----
        {
            const int key = t >> 2;
            const int at0 = (t & 3) * 4;
            const float* ksrc = kg + (size_t)(kv0 + key) * ND + at0 * 4;
            const float* vsrc = vg + (size_t)(kv0 + key) * ND + at0 * 4;
            uint32_t* kp = (uint32_t*)&Ks[key * ALDS + at0 * 4];
#pragma unroll
            for (int j = 0; j < 4; j++) {
                float4 kv4 = *(const float4*)(ksrc + j * 4);
                kp[j * 4 + 0] = f2tf(kv4.x);
                kp[j * 4 + 1] = f2tf(kv4.y);
                kp[j * 4 + 2] = f2tf(kv4.z);
                kp[j * 4 + 3] = f2tf(kv4.w);
                float4 vv4 = *(const float4*)(vsrc + j * 4);
                const int d0 = (at0 + j) * 4;
                uint32_t* vsp = (uint32_t*)Vs;
                vsp[(d0 + 0) * ALDS + key] = f2tf(vv4.x);
                vsp[(d0 + 1) * ALDS + key] = f2tf(vv4.y);
                vsp[(d0 + 2) * ALDS + key] = f2tf(vv4.z);
                vsp[(d0 + 3) * ALDS + key] = f2tf(vv4.w);
            }
        }
        __syncthreads();

        // ---- S = Q K^T (warp: 16 rows x 64 keys) ----
        float s[8][4];
#pragma unroll
        for (int ni = 0; ni < 8; ni++)
#pragma unroll
            for (int j = 0; j < 4; j++) s[ni][j] = 0.0f;

#pragma unroll
        for (int ks = 0; ks < 8; ks++) {
            const int kc = ks * 8;
            uint32_t a[4];
            ldm_x4(a[0], a[1], a[2], a[3],
                   qs_base + ((w * 16 + a_row) * ALDS + kc + a_col) * 4);
            uint32_t bb[4][4];
#pragma unroll
            for (int np = 0; np < 4; np++)
                ldm_x4(bb[np][0], bb[np][1], bb[np][2], bb[np][3],
                       ks_base + ((np * 16 + b_row) * ALDS + kc + b_col) * 4);
#pragma unroll
            for (int ni = 0; ni < 8; ni++)
                mma_tf32(s[ni], a, bb[ni >> 1][(ni & 1) * 2], bb[ni >> 1][(ni & 1) * 2 + 1]);
        }

        // ---- P = exp(S); row partial sums; stash tf32 P ----
#pragma unroll
        for (int ni = 0; ni < 8; ni++) {
            float e0 = __expf(s[ni][0]);
            float e1 = __expf(s[ni][1]);
            float e2 = __expf(s[ni][2]);
            float e3 = __expf(s[ni][3]);
            lsum0 += e0 + e1;
            lsum1 += e2 + e3;
            uint32_t* pp0 = (uint32_t*)&Ps[prow0 * ALDS + ni * 8 + pcol0];
            uint32_t* pp1 = (uint32_t*)&Ps[(prow0 + 8) * ALDS + ni * 8 + pcol0];
            pp0[0] = f2tf(e0); pp0[1] = f2tf(e1);
            pp1[0] = f2tf(e2); pp1[1] = f2tf(e3);
        }
        __syncthreads();

        // ---- O += P V (warp: 16 rows x 64 d) ----
#pragma unroll
        for (int ks = 0; ks < 8; ks++) {
            const int kc = ks * 8;       // key offset within tile
            uint32_t a[4];
            ldm_x4(a[0], a[1], a[2], a[3],
                   ps_base + ((w * 16 + a_row) * ALDS + kc + a_col) * 4);
            uint32_t bb[4][4];
#pragma unroll
            for (int np = 0; np < 4; np++)
                ldm_x4(bb[np][0], bb[np][1], bb[np][2], bb[np][3],
                       vs_base + ((np * 16 + b_row) * ALDS + kc + b_col) * 4);
#pragma unroll
            for (int ni = 0; ni < 8; ni++)
                mma_tf32(o[ni], a, bb[ni >> 1][(ni & 1) * 2], bb[ni >> 1][(ni & 1) * 2 + 1]);
        }
    }

    // ---- reduce row sums across the 4 lanes of each quad ----
    lsum0 += __shfl_xor_sync(0xffffffffu, lsum0, 1);
    lsum0 += __shfl_xor_sync(0xffffffffu, lsum0, 2);
    lsum1 += __shfl_xor_sync(0xffffffffu, lsum1, 1);
    lsum1 += __shfl_xor_sync(0xffffffffu, lsum1, 2);
    const float inv0 = 1.0f / lsum0;
    const float inv1 = 1.0f / lsum1;

    // ---- write O (token-major [tok][C]) ----
    const int grow0 = qtile * 128 + prow0;
#pragma unroll
    for (int ni = 0; ni < 8; ni++) {
        const int col = h * ND + ni * 8 + pcol0;
        float2 v01 = make_float2(o[ni][0] * inv0, o[ni][1] * inv0);
        float2 v23 = make_float2(o[ni][2] * inv1, o[ni][3] * inv1);
        *(float2*)(att + (size_t)(b * NN + grow0) * NC + col)     = v01;
        *(float2*)(att + (size_t)(b * NN + grow0 + 8) * NC + col) = v23;
    }
}

// =============================================================================
// Launch
// =============================================================================
extern "C" void kernel_launch(void* const* d_in, const int* in_sizes, int n_in,
                              void* d_out, int out_size)
{
    (void)in_sizes; (void)n_in; (void)out_size;
    const float* x      = (const float*)d_in[0];
    const float* qkv_w  = (const float*)d_in[1];
    const float* temp   = (const float*)d_in[2];
    const float* proj_w = (const float*)d_in[3];
    const float* proj_b = (const float*)d_in[4];
    float* out = (float*)d_out;

    float *p_qkv, *p_q, *p_k, *p_v, *p_att;
    cudaGetSymbolAddress((void**)&p_qkv, g_qkv);
    cudaGetSymbolAddress((void**)&p_q,   g_q);
    cudaGetSymbolAddress((void**)&p_k,   g_k);
    cudaGetSymbolAddress((void**)&p_v,   g_v);
    cudaGetSymbolAddress((void**)&p_att, g_att);

    cudaFuncSetAttribute(attn_kernel,
                         cudaFuncAttributeMaxDynamicSharedMemorySize,
                         ATTN_SMEM_BYTES);

    gemm_tf32<false><<<dim3(3 * NC / 128, NTOK / 128), 256>>>(
        x, qkv_w, nullptr, p_qkv, NTOK, 3 * NC, NC);

    norm_split_kernel<<<NTOK, 256>>>(p_qkv, p_q, p_k, p_v);

    attn_kernel<<<dim3(NN / 128, NB * NH), 256, ATTN_SMEM_BYTES>>>(
        p_q, p_k, p_v, temp, p_att);

    gemm_tf32<true><<<dim3(NC / 128, NTOK / 128), 256>>>(
        p_att, proj_w, proj_b, out, NTOK, NC, NC);
}

// round 5
// speedup vs baseline: 2.9635x; 1.1879x over previous
#include <cuda_runtime.h>
#include <math.h>
#include <stdint.h>

// B=2, N=2048, C=1024, H=16, D=64
#define NB 2
#define NN 2048
#define NC 1024
#define NH 16
#define ND 64
#define NTOK (NB * NN)

// ---------------- scratch ----------------
__device__ uint32_t g_xt[NTOK * NC];         // x in tf32 bits
__device__ uint32_t g_wqkv[3 * NC * NC];     // qkv_w in tf32 bits
__device__ uint32_t g_wproj[NC * NC];        // proj_w in tf32 bits
__device__ float    g_qkv[NTOK * 3 * NC];    // GEMM1 output (fp32)
__device__ uint32_t g_q[NTOK * NC];          // [bh][n][d]   tf32 (scaled)
__device__ uint32_t g_k[NTOK * NC];          // [bh][n][d]   tf32 (scaled)
__device__ uint32_t g_v[NTOK * NC];          // [bh][d][n]   tf32 TRANSPOSED
__device__ uint32_t g_att[NTOK * NC];        // attention out, tf32, token-major

// ---------------- PTX helpers ----------------
__device__ __forceinline__ uint32_t f2tf(float f) {
    uint32_t u;
    asm("cvt.rna.tf32.f32 %0, %1;" : "=r"(u) : "f"(f));
    return u;
}
__device__ __forceinline__ uint32_t smem_u32(const void* p) {
    return (uint32_t)__cvta_generic_to_shared(p);
}
__device__ __forceinline__ void ldm_x4(uint32_t& r0, uint32_t& r1,
                                       uint32_t& r2, uint32_t& r3, uint32_t addr) {
    asm volatile("ldmatrix.sync.aligned.m8n8.x4.shared.b16 {%0,%1,%2,%3}, [%4];"
                 : "=r"(r0), "=r"(r1), "=r"(r2), "=r"(r3) : "r"(addr));
}
__device__ __forceinline__ void mma_tf32(float* c, const uint32_t* a,
                                         uint32_t b0, uint32_t b1) {
    asm volatile(
        "mma.sync.aligned.m16n8k8.row.col.f32.tf32.tf32.f32 "
        "{%0,%1,%2,%3}, {%4,%5,%6,%7}, {%8,%9}, {%0,%1,%2,%3};"
        : "+f"(c[0]), "+f"(c[1]), "+f"(c[2]), "+f"(c[3])
        : "r"(a[0]), "r"(a[1]), "r"(a[2]), "r"(a[3]), "r"(b0), "r"(b1));
}
__device__ __forceinline__ void cp_async16(uint32_t saddr, const void* gptr) {
    asm volatile("cp.async.cg.shared.global [%0], [%1], 16;"
                 :: "r"(saddr), "l"(gptr));
}
#define CP_COMMIT() asm volatile("cp.async.commit_group;" ::: "memory")
#define CP_WAIT(n)  asm volatile("cp.async.wait_group %0;" :: "n"(n) : "memory")

// =============================================================================
// fp32 -> tf32-bits conversion (RNA), vectorized
// =============================================================================
__global__ __launch_bounds__(256) void cvt_tf32_kernel(
    const float4* __restrict__ src, uint4* __restrict__ dst, int n4)
{
    int i = blockIdx.x * 256 + threadIdx.x;
    if (i < n4) {
        float4 v = src[i];
        dst[i] = make_uint4(f2tf(v.x), f2tf(v.y), f2tf(v.z), f2tf(v.w));
    }
}

// =============================================================================
// Pipelined TF32 GEMM (cp.async, 3 stages): C[M,N] = A[M,K]*B[N,K]^T (+bias)
// A,B already tf32 bits in global. Block 128x128, Ktile=16, 8 warps (2x4),
// warp 64x32. SMEM rows padded to 20 floats (odd 16B atoms -> ldmatrix clean).
// =============================================================================
#define GLDS 20
#define G_STAGE_FLOATS (128 * GLDS * 2)     // A tile + B tile = 5120 floats
#define G_STAGE_BYTES  (G_STAGE_FLOATS * 4) // 20480
#define G_SMEM_TOTAL   (3 * G_STAGE_BYTES)  // 61440

template <bool HAS_BIAS>
__global__ __launch_bounds__(256) void gemm_tc(
    const uint32_t* __restrict__ A, const uint32_t* __restrict__ Bm,
    const float* __restrict__ bias, float* __restrict__ C,
    int M, int Nc, int K)
{
    extern __shared__ __align__(128) float gsm[];
    const uint32_t sbase0 = smem_u32(gsm);

    const int t = threadIdx.x;
    const int w = t >> 5, lane = t & 31;
    const int wm = w >> 2, wn = w & 3;

    const uint32_t* Ab = A  + (size_t)(blockIdx.y * 128) * K;
    const uint32_t* Bb = Bm + (size_t)(blockIdx.x * 128) * K;

    const int a_row = (lane & 7) + ((lane >> 3) & 1) * 8;
    const int a_col = ((lane >> 4) << 2);
    const int b_row = (lane & 7) + ((lane >> 4) << 3);
    const int b_col = ((lane >> 3) & 1) * 4;

    float acc[4][4][4];
#pragma unroll
    for (int mi = 0; mi < 4; mi++)
#pragma unroll
        for (int ni = 0; ni < 4; ni++)
#pragma unroll
            for (int j = 0; j < 4; j++) acc[mi][ni][j] = 0.0f;

    const int NT = K >> 4;

    // async producer: 1024 16B-chunks per stage (512 A, 512 B), 4 per thread
    auto issue = [&](int kt) {
        const int stage = kt % 3;
        const uint32_t sb = sbase0 + stage * G_STAGE_BYTES;
#pragma unroll
        for (int i = 0; i < 4; i++) {
            int c = t + i * 256;
            int mat = c >> 9;
            int r   = (c >> 2) & 127;
            int q   = c & 3;
            const uint32_t* g = (mat ? Bb : Ab) + (size_t)r * K + kt * 16 + q * 4;
            uint32_t sa = sb + (uint32_t)(mat * (128 * GLDS) + r * GLDS + q * 4) * 4;
            cp_async16(sa, g);
        }
        CP_COMMIT();
    };

    issue(0); issue(1); issue(2);

    for (int kt = 0; kt < NT; kt++) {
        const int stage = kt % 3;
        const uint32_t as = sbase0 + stage * G_STAGE_BYTES;
        const uint32_t bs = as + 128 * GLDS * 4;

        CP_WAIT(2);
        __syncthreads();

#pragma unroll
        for (int ks = 0; ks < 2; ks++) {
            const int kc = ks * 8;
            uint32_t a[4][4];
#pragma unroll
            for (int mi = 0; mi < 4; mi++)
                ldm_x4(a[mi][0], a[mi][1], a[mi][2], a[mi][3],
                       as + ((wm * 64 + mi * 16 + a_row) * GLDS + kc + a_col) * 4);
            uint32_t b[2][4];
#pragma unroll
            for (int np = 0; np < 2; np++)
                ldm_x4(b[np][0], b[np][1], b[np][2], b[np][3],
                       bs + ((wn * 32 + np * 16 + b_row) * GLDS + kc + b_col) * 4);
#pragma unroll
            for (int mi = 0; mi < 4; mi++)
#pragma unroll
                for (int ni = 0; ni < 4; ni++)
                    mma_tf32(acc[mi][ni], a[mi],
                             b[ni >> 1][(ni & 1) * 2], b[ni >> 1][(ni & 1) * 2 + 1]);
        }
        __syncthreads();
        if (kt + 3 < NT) issue(kt + 3);
    }

    // epilogue (fp32 out)
    const int erow0 = blockIdx.y * 128 + wm * 64 + (lane >> 2);
    const int ecol0 = blockIdx.x * 128 + wn * 32 + (lane & 3) * 2;
#pragma unroll
    for (int mi = 0; mi < 4; mi++) {
#pragma unroll
        for (int ni = 0; ni < 4; ni++) {
            int r = erow0 + mi * 16;
            int c = ecol0 + ni * 8;
            float2 v01 = make_float2(acc[mi][ni][0], acc[mi][ni][1]);
            float2 v23 = make_float2(acc[mi][ni][2], acc[mi][ni][3]);
            if (HAS_BIAS) {
                float b0 = bias[c], b1 = bias[c + 1];
                v01.x += b0; v01.y += b1;
                v23.x += b0; v23.y += b1;
            }
            *(float2*)(C + (size_t)r * Nc + c)       = v01;
            *(float2*)(C + (size_t)(r + 8) * Nc + c) = v23;
        }
    }
}

// =============================================================================
// Normalize q,k over full C; scale 1/sqrt(D); emit tf32. v -> TRANSPOSED
// layout [bh][d][n] (tf32). One block per token.
// =============================================================================
__global__ __launch_bounds__(256) void norm_split_kernel(
    const float* __restrict__ qkv,
    uint32_t* __restrict__ q, uint32_t* __restrict__ k, uint32_t* __restrict__ v)
{
    const int tok = blockIdx.x;
    const int b = tok >> 11;
    const int n = tok & 2047;
    const float* row = qkv + (size_t)tok * (3 * NC);
    const int t = threadIdx.x;

    float4 qv = *(const float4*)(row + t * 4);
    float4 kv = *(const float4*)(row + NC + t * 4);
    float4 vv = *(const float4*)(row + 2 * NC + t * 4);

    float sq = qv.x * qv.x + qv.y * qv.y + qv.z * qv.z + qv.w * qv.w;
    float sk = kv.x * kv.x + kv.y * kv.y + kv.z * kv.z + kv.w * kv.w;
#pragma unroll
    for (int m = 16; m > 0; m >>= 1) {
        sq += __shfl_xor_sync(0xffffffffu, sq, m);
        sk += __shfl_xor_sync(0xffffffffu, sk, m);
    }
    __shared__ float red[2][8];
    const int warp = t >> 5, lane = t & 31;
    if (lane == 0) { red[0][warp] = sq; red[1][warp] = sk; }
    __syncthreads();
    float sqt = 0.f, skt = 0.f;
#pragma unroll
    for (int w = 0; w < 8; w++) { sqt += red[0][w]; skt += red[1][w]; }

    const float qs = 0.125f / fmaxf(sqrtf(sqt), 1e-12f);
    const float ks = 0.125f / fmaxf(sqrtf(skt), 1e-12f);

    const int h = t >> 4;
    const int d = (t & 15) * 4;
    const size_t qoff = ((size_t)(b * NH + h) * NN + n) * ND + d;
    uint4 qo = make_uint4(f2tf(qv.x * qs), f2tf(qv.y * qs),
                          f2tf(qv.z * qs), f2tf(qv.w * qs));
    uint4 ko = make_uint4(f2tf(kv.x * ks), f2tf(kv.y * ks),
                          f2tf(kv.z * ks), f2tf(kv.w * ks));
    *(uint4*)&q[qoff] = qo;
    *(uint4*)&k[qoff] = ko;

    // transposed v: [bh][d][n]
    const size_t vbase = ((size_t)(b * NH + h) * ND + d) * NN + n;
    v[vbase]          = f2tf(vv.x);
    v[vbase + NN]     = f2tf(vv.y);
    v[vbase + 2 * NN] = f2tf(vv.z);
    v[vbase + 3 * NN] = f2tf(vv.w);
}

// =============================================================================
// Attention, cp.async double-buffered K/V. |logit|<=1/64 -> no-max softmax.
// 8 warps x 16 q-rows; 64-key tiles; q/k tf32 [bh][n][d]; v tf32 [bh][d][n].
// SMEM (floats): Qs[128][68] | Kst[2][64][68] | Vst[2][64][68] | Ps[128][68]
// =============================================================================
#define ALDS 68
#define ATTN_SMEM_FLOATS (128 * ALDS + 2 * 64 * ALDS + 2 * 64 * ALDS + 128 * ALDS)
#define ATTN_SMEM_BYTES  (ATTN_SMEM_FLOATS * 4)
#define QS_OFF  0
#define KST_OFF (128 * ALDS)
#define VST_OFF (KST_OFF + 2 * 64 * ALDS)
#define PS_OFF  (VST_OFF + 2 * 64 * ALDS)

__global__ __launch_bounds__(256) void attn_kernel(
    const uint32_t* __restrict__ q, const uint32_t* __restrict__ k,
    const uint32_t* __restrict__ v, const float* __restrict__ temp,
    uint32_t* __restrict__ att)
{
    extern __shared__ __align__(128) float smemf[];
    const uint32_t sb = smem_u32(smemf);
    const uint32_t qs_base = sb + QS_OFF * 4;
    const uint32_t ps_base = sb + PS_OFF * 4;

    const int t = threadIdx.x;
    const int w = t >> 5, lane = t & 31;
    const int qtile = blockIdx.x;
    const int bh = blockIdx.y;
    const int b = bh >> 4, h = bh & 15;

    const float invT = 1.0f / temp[h];
    const uint32_t* qg = q + ((size_t)bh * NN + qtile * 128) * ND;
    const uint32_t* kg = k + (size_t)bh * NN * ND;
    const uint32_t* vg = v + (size_t)bh * ND * NN;   // transposed [d][n]

    const int a_row = (lane & 7) + ((lane >> 3) & 1) * 8;
    const int a_col = ((lane >> 4) << 2);
    const int b_row = (lane & 7) + ((lane >> 4) << 3);
    const int b_col = ((lane >> 3) & 1) * 4;

    // ---- load Q tile once (scale by invT, re-round) ----
    {
        const int row = t >> 1;
        const int at0 = (t & 1) * 8;
        uint32_t* qp = (uint32_t*)(smemf + QS_OFF + row * ALDS + at0 * 4);
        const uint32_t* src = qg + (size_t)row * ND + at0 * 4;
#pragma unroll
        for (int j = 0; j < 8; j++) {
            uint4 raw = *(const uint4*)(src + j * 4);
            qp[j * 4 + 0] = f2tf(__uint_as_float(raw.x) * invT);
            qp[j * 4 + 1] = f2tf(__uint_as_float(raw.y) * invT);
            qp[j * 4 + 2] = f2tf(__uint_as_float(raw.z) * invT);
            qp[j * 4 + 3] = f2tf(__uint_as_float(raw.w) * invT);
        }
    }

    // async K/V tile producer: 2048 16B-chunks per stage (1024 K + 1024 V),
    // 8 per thread. K tile row = 64 floats = 16 chunks; 64 rows each.
    auto issue = [&](int it) {
        const int stage = it & 1;
        const int kv0 = it * 64;
        const uint32_t kb = sb + (KST_OFF + stage * 64 * ALDS) * 4;
        const uint32_t vb = sb + (VST_OFF + stage * 64 * ALDS) * 4;
#pragma unroll
        for (int i = 0; i < 8; i++) {
            int c = t + i * 256;       // 0..2047
            int mat = c >> 10;         // 0 = K, 1 = V
            int r   = (c >> 4) & 63;   // tile row
            int qq  = c & 15;          // 16B chunk within row
            if (!mat)
                cp_async16(kb + (uint32_t)(r * ALDS + qq * 4) * 4,
                           kg + (size_t)(kv0 + r) * ND + qq * 4);
            else
                cp_async16(vb + (uint32_t)(r * ALDS + qq * 4) * 4,
                           vg + (size_t)r * NN + kv0 + qq * 4);
        }
        CP_COMMIT();
    };

    float o[8][4];
#pragma unroll
    for (int ni = 0; ni < 8; ni++)
#pragma unroll
        for (int j = 0; j < 4; j++) o[ni][j] = 0.0f;
    float lsum0 = 0.0f, lsum1 = 0.0f;

    const int prow0 = w * 16 + (lane >> 2);
    const int pcol0 = (lane & 3) * 2;

    issue(0); issue(1);

    for (int it = 0; it < NN / 64; it++) {
        const int stage = it & 1;
        const uint32_t ks_base = sb + (KST_OFF + stage * 64 * ALDS) * 4;
        const uint32_t vs_base = sb + (VST_OFF + stage * 64 * ALDS) * 4;

        CP_WAIT(1);
        __syncthreads();      // tile visible to all; also covers Q on it=0

        // ---- S = Q K^T (warp: 16 rows x 64 keys) ----
        float s[8][4];
#pragma unroll
        for (int ni = 0; ni < 8; ni++)
#pragma unroll
            for (int j = 0; j < 4; j++) s[ni][j] = 0.0f;

#pragma unroll
        for (int ks = 0; ks < 8; ks++) {
            const int kc = ks * 8;
            uint32_t a[4];
            ldm_x4(a[0], a[1], a[2], a[3],
                   qs_base + ((w * 16 + a_row) * ALDS + kc + a_col) * 4);
            uint32_t bb[4][4];
#pragma unroll
            for (int np = 0; np < 4; np++)
                ldm_x4(bb[np][0], bb[np][1], bb[np][2], bb[np][3],
                       ks_base + ((np * 16 + b_row) * ALDS + kc + b_col) * 4);
#pragma unroll
            for (int ni = 0; ni < 8; ni++)
                mma_tf32(s[ni], a, bb[ni >> 1][(ni & 1) * 2],
                         bb[ni >> 1][(ni & 1) * 2 + 1]);
        }

        // ---- P = exp(S); partial row sums; stash tf32 P (warp-private) ----
#pragma unroll
        for (int ni = 0; ni < 8; ni++) {
            float e0 = __expf(s[ni][0]);
            float e1 = __expf(s[ni][1]);
            float e2 = __expf(s[ni][2]);
            float e3 = __expf(s[ni][3]);
            lsum0 += e0 + e1;
            lsum1 += e2 + e3;
            uint32_t* pp0 = (uint32_t*)(smemf + PS_OFF + prow0 * ALDS + ni * 8 + pcol0);
            uint32_t* pp1 = (uint32_t*)(smemf + PS_OFF + (prow0 + 8) * ALDS + ni * 8 + pcol0);
            pp0[0] = f2tf(e0); pp0[1] = f2tf(e1);
            pp1[0] = f2tf(e2); pp1[1] = f2tf(e3);
        }
        __syncwarp();          // P rows are warp-local

        // ---- O += P V (warp: 16 rows x 64 d) ----
#pragma unroll
        for (int ks = 0; ks < 8; ks++) {
            const int kc = ks * 8;
            uint32_t a[4];
            ldm_x4(a[0], a[1], a[2], a[3],
                   ps_base + ((w * 16 + a_row) * ALDS + kc + a_col) * 4);
            uint32_t bb[4][4];
#pragma unroll
            for (int np = 0; np < 4; np++)
                ldm_x4(bb[np][0], bb[np][1], bb[np][2], bb[np][3],
                       vs_base + ((np * 16 + b_row) * ALDS + kc + b_col) * 4);
#pragma unroll
            for (int ni = 0; ni < 8; ni++)
                mma_tf32(o[ni], a, bb[ni >> 1][(ni & 1) * 2],
                         bb[ni >> 1][(ni & 1) * 2 + 1]);
        }

        __syncthreads();       // all warps done with this K/V stage
        if (it + 2 < NN / 64) issue(it + 2);
    }

    // ---- reduce row sums across each quad ----
    lsum0 += __shfl_xor_sync(0xffffffffu, lsum0, 1);
    lsum0 += __shfl_xor_sync(0xffffffffu, lsum0, 2);
    lsum1 += __shfl_xor_sync(0xffffffffu, lsum1, 1);
    lsum1 += __shfl_xor_sync(0xffffffffu, lsum1, 2);
    const float inv0 = 1.0f / lsum0;
    const float inv1 = 1.0f / lsum1;

    // ---- write O as tf32, token-major [tok][C] ----
    const int grow0 = qtile * 128 + prow0;
#pragma unroll
    for (int ni = 0; ni < 8; ni++) {
        const int col = h * ND + ni * 8 + pcol0;
        uint2 v01 = make_uint2(f2tf(o[ni][0] * inv0), f2tf(o[ni][1] * inv0));
        uint2 v23 = make_uint2(f2tf(o[ni][2] * inv1), f2tf(o[ni][3] * inv1));
        *(uint2*)(att + (size_t)(b * NN + grow0) * NC + col)     = v01;
        *(uint2*)(att + (size_t)(b * NN + grow0 + 8) * NC + col) = v23;
    }
}

// =============================================================================
// Launch
// =============================================================================
extern "C" void kernel_launch(void* const* d_in, const int* in_sizes, int n_in,
                              void* d_out, int out_size)
{
    (void)in_sizes; (void)n_in; (void)out_size;
    const float* x      = (const float*)d_in[0];
    const float* qkv_w  = (const float*)d_in[1];
    const float* temp   = (const float*)d_in[2];
    const float* proj_w = (const float*)d_in[3];
    const float* proj_b = (const float*)d_in[4];
    float* out = (float*)d_out;

    uint32_t *p_xt, *p_wqkv, *p_wproj, *p_q, *p_k, *p_v, *p_att;
    float *p_qkv;
    cudaGetSymbolAddress((void**)&p_xt,    g_xt);
    cudaGetSymbolAddress((void**)&p_wqkv,  g_wqkv);
    cudaGetSymbolAddress((void**)&p_wproj, g_wproj);
    cudaGetSymbolAddress((void**)&p_qkv,   g_qkv);
    cudaGetSymbolAddress((void**)&p_q,     g_q);
    cudaGetSymbolAddress((void**)&p_k,     g_k);
    cudaGetSymbolAddress((void**)&p_v,     g_v);
    cudaGetSymbolAddress((void**)&p_att,   g_att);

    cudaFuncSetAttribute(gemm_tc<false>,
                         cudaFuncAttributeMaxDynamicSharedMemorySize, G_SMEM_TOTAL);
    cudaFuncSetAttribute(gemm_tc<true>,
                         cudaFuncAttributeMaxDynamicSharedMemorySize, G_SMEM_TOTAL);
    cudaFuncSetAttribute(attn_kernel,
                         cudaFuncAttributeMaxDynamicSharedMemorySize, ATTN_SMEM_BYTES);

    // 0) convert inputs to tf32 bits
    cvt_tf32_kernel<<<(NTOK * NC / 4 + 255) / 256, 256>>>(
        (const float4*)x, (uint4*)p_xt, NTOK * NC / 4);
    cvt_tf32_kernel<<<(3 * NC * NC / 4 + 255) / 256, 256>>>(
        (const float4*)qkv_w, (uint4*)p_wqkv, 3 * NC * NC / 4);
    cvt_tf32_kernel<<<(NC * NC / 4 + 255) / 256, 256>>>(
        (const float4*)proj_w, (uint4*)p_wproj, NC * NC / 4);

    // 1) QKV GEMM
    gemm_tc<false><<<dim3(3 * NC / 128, NTOK / 128), 256, G_SMEM_TOTAL>>>(
        p_xt, p_wqkv, nullptr, p_qkv, NTOK, 3 * NC, NC);

    // 2) normalize + head split (q,k scaled tf32; v transposed tf32)
    norm_split_kernel<<<NTOK, 256>>>(p_qkv, p_q, p_k, p_v);

    // 3) attention
    attn_kernel<<<dim3(NN / 128, NB * NH), 256, ATTN_SMEM_BYTES>>>(
        p_q, p_k, p_v, temp, p_att);

    // 4) projection
    gemm_tc<true><<<dim3(NC / 128, NTOK / 128), 256, G_SMEM_TOTAL>>>(
        p_att, p_wproj, proj_b, out, NTOK, NC, NC);
}

// round 6
// speedup vs baseline: 5.7586x; 1.9432x over previous
#include <cuda_runtime.h>
#include <cuda_fp16.h>
#include <math.h>
#include <stdint.h>

// B=2, N=2048, C=1024, H=16, D=64
#define NB 2
#define NN 2048
#define NC 1024
#define NH 16
#define ND 64
#define NTOK (NB * NN)

// ---------------- scratch ----------------
__device__ __half g_xt[NTOK * NC];          // x fp16
__device__ __half g_wqkv[3 * NC * NC];      // qkv_w fp16
__device__ __half g_wproj[NC * NC];         // proj_w fp16
__device__ float  g_qkv[NTOK * 3 * NC];     // GEMM1 out fp32 (norm needs accuracy)
__device__ __half g_q[NTOK * NC];           // [bh][n][d] fp16, scaled by 0.125/T[h]
__device__ __half g_k[NTOK * NC];           // [bh][n][d] fp16, scaled by 0.125
__device__ __half g_v[NTOK * NC];           // [bh][d][n] fp16 TRANSPOSED
__device__ __half g_att[NTOK * NC];         // attention out fp16, token-major

// ---------------- PTX helpers ----------------
__device__ __forceinline__ uint32_t smem_u32(const void* p) {
    return (uint32_t)__cvta_generic_to_shared(p);
}
__device__ __forceinline__ void ldm_x4(uint32_t& r0, uint32_t& r1,
                                       uint32_t& r2, uint32_t& r3, uint32_t addr) {
    asm volatile("ldmatrix.sync.aligned.m8n8.x4.shared.b16 {%0,%1,%2,%3}, [%4];"
                 : "=r"(r0), "=r"(r1), "=r"(r2), "=r"(r3) : "r"(addr));
}
__device__ __forceinline__ void mma_f16(float* c, const uint32_t* a,
                                        uint32_t b0, uint32_t b1) {
    asm volatile(
        "mma.sync.aligned.m16n8k16.row.col.f32.f16.f16.f32 "
        "{%0,%1,%2,%3}, {%4,%5,%6,%7}, {%8,%9}, {%0,%1,%2,%3};"
        : "+f"(c[0]), "+f"(c[1]), "+f"(c[2]), "+f"(c[3])
        : "r"(a[0]), "r"(a[1]), "r"(a[2]), "r"(a[3]), "r"(b0), "r"(b1));
}
__device__ __forceinline__ void cp_async16(uint32_t saddr, const void* gptr) {
    asm volatile("cp.async.cg.shared.global [%0], [%1], 16;"
                 :: "r"(saddr), "l"(gptr));
}
#define CP_COMMIT() asm volatile("cp.async.commit_group;" ::: "memory")
#define CP_WAIT(n)  asm volatile("cp.async.wait_group %0;" :: "n"(n) : "memory")

__device__ __forceinline__ uint32_t h2_bits(float a, float b) {
    __half2 h = __floats2half2_rn(a, b);
    return *(uint32_t*)&h;
}

// =============================================================================
// fp32 -> fp16 conversion, 8 elems/thread
// =============================================================================
__global__ __launch_bounds__(256) void cvt_f16_kernel(
    const float4* __restrict__ src, uint4* __restrict__ dst, int n8)
{
    int i = blockIdx.x * 256 + threadIdx.x;
    if (i < n8) {
        float4 a = src[2 * i], b = src[2 * i + 1];
        uint4 o;
        o.x = h2_bits(a.x, a.y); o.y = h2_bits(a.z, a.w);
        o.z = h2_bits(b.x, b.y); o.w = h2_bits(b.z, b.w);
        dst[i] = o;
    }
}

// =============================================================================
// FP16 GEMM: C[M,N] = A[M,K]*B[N,K]^T (+bias), fp32 accum/out.
// Block 128x128, Ktile=32 halves, 8 warps (2x4), warp 64x32.
// 4-stage cp.async ring, ONE __syncthreads per iter, empty-commit tail.
// SMEM rows: 40 halves (5x16B atoms, odd -> ldmatrix conflict-free).
// =============================================================================
#define GKH   32
#define GROWH 40
#define G_STAGE_BYTES (128 * GROWH * 2 * 2)    // A + B = 20480
#define G_SMEM_TOTAL  (4 * G_STAGE_BYTES)      // 81920

template <bool HAS_BIAS>
__global__ __launch_bounds__(256) void gemm_f16(
    const __half* __restrict__ A, const __half* __restrict__ Bm,
    const float* __restrict__ bias, float* __restrict__ C,
    int M, int Nc, int K)
{
    extern __shared__ __align__(128) char gsm[];
    const uint32_t sbase0 = smem_u32(gsm);

    const int t = threadIdx.x;
    const int w = t >> 5, lane = t & 31;
    const int wm = w >> 2, wn = w & 3;

    const __half* Ab = A  + (size_t)(blockIdx.y * 128) * K;
    const __half* Bb = Bm + (size_t)(blockIdx.x * 128) * K;

    // ldmatrix lane offsets (halves)
    const int a_row  = (lane & 7) + ((lane >> 3) & 1) * 8;
    const int a_colh = (lane >> 4) << 3;
    const int b_row  = (lane & 7) + ((lane >> 4) << 3);
    const int b_colh = ((lane >> 3) & 1) * 8;

    float acc[4][4][4];
#pragma unroll
    for (int mi = 0; mi < 4; mi++)
#pragma unroll
        for (int ni = 0; ni < 4; ni++)
#pragma unroll
            for (int j = 0; j < 4; j++) acc[mi][ni][j] = 0.0f;

    const int NT = K >> 5;   // Ktile = 32 halves

    // producer: 1024 16B chunks/stage (A 512 + B 512), 4/thread
    auto issue = [&](int kt) {
        const int stage = kt & 3;
        const uint32_t sb = sbase0 + stage * G_STAGE_BYTES;
#pragma unroll
        for (int i = 0; i < 4; i++) {
            int c = t + i * 256;
            int mat = c >> 9;            // 0=A, 1=B
            int r   = (c >> 2) & 127;
            int q   = c & 3;             // 16B chunk (8 halves)
            const __half* g = (mat ? Bb : Ab) + (size_t)r * K + kt * GKH + q * 8;
            uint32_t sa = sb + (uint32_t)(mat * (128 * GROWH) + r * GROWH + q * 8) * 2;
            cp_async16(sa, g);
        }
        CP_COMMIT();
    };

    issue(0); issue(1); issue(2);

    for (int kt = 0; kt < NT; kt++) {
        const uint32_t as = sbase0 + (kt & 3) * G_STAGE_BYTES;
        const uint32_t bs = as + 128 * GROWH * 2;

        CP_WAIT(2);
        __syncthreads();

#pragma unroll
        for (int ks = 0; ks < 2; ks++) {
            const int kc = ks * 16;
            uint32_t a[4][4];
#pragma unroll
            for (int mi = 0; mi < 4; mi++)
                ldm_x4(a[mi][0], a[mi][1], a[mi][2], a[mi][3],
                       as + ((wm * 64 + mi * 16 + a_row) * GROWH + kc + a_colh) * 2);
            uint32_t b[2][4];
#pragma unroll
            for (int np = 0; np < 2; np++)
                ldm_x4(b[np][0], b[np][1], b[np][2], b[np][3],
                       bs + ((wn * 32 + np * 16 + b_row) * GROWH + kc + b_colh) * 2);
#pragma unroll
            for (int mi = 0; mi < 4; mi++)
#pragma unroll
                for (int ni = 0; ni < 4; ni++)
                    mma_f16(acc[mi][ni], a[mi],
                            b[ni >> 1][(ni & 1) * 2], b[ni >> 1][(ni & 1) * 2 + 1]);
        }

        // write-stage (kt+3)&3 was last read at kt-1; all threads passed the
        // sync above after that -> no second sync needed. Commit every iter
        // (empty in tail) to keep wait_group(2) arithmetic exact.
        if (kt + 3 < NT) issue(kt + 3);
        else             CP_COMMIT();
    }

    // epilogue (fp32)
    const int erow0 = blockIdx.y * 128 + wm * 64 + (lane >> 2);
    const int ecol0 = blockIdx.x * 128 + wn * 32 + (lane & 3) * 2;
#pragma unroll
    for (int mi = 0; mi < 4; mi++) {
#pragma unroll
        for (int ni = 0; ni < 4; ni++) {
            int r = erow0 + mi * 16;
            int c = ecol0 + ni * 8;
            float2 v01 = make_float2(acc[mi][ni][0], acc[mi][ni][1]);
            float2 v23 = make_float2(acc[mi][ni][2], acc[mi][ni][3]);
            if (HAS_BIAS) {
                float b0 = bias[c], b1 = bias[c + 1];
                v01.x += b0; v01.y += b1;
                v23.x += b0; v23.y += b1;
            }
            *(float2*)(C + (size_t)r * Nc + c)       = v01;
            *(float2*)(C + (size_t)(r + 8) * Nc + c) = v23;
        }
    }
}

// =============================================================================
// Normalize q,k over full C; q scaled 0.125/T[h], k scaled 0.125; fp16 out.
// v -> transposed [bh][d][n] fp16.
// =============================================================================
__global__ __launch_bounds__(256) void norm_split_kernel(
    const float* __restrict__ qkv, const float* __restrict__ temp,
    __half* __restrict__ q, __half* __restrict__ k, __half* __restrict__ v)
{
    const int tok = blockIdx.x;
    const int b = tok >> 11;
    const int n = tok & 2047;
    const float* row = qkv + (size_t)tok * (3 * NC);
    const int t = threadIdx.x;

    float4 qv = *(const float4*)(row + t * 4);
    float4 kv = *(const float4*)(row + NC + t * 4);
    float4 vv = *(const float4*)(row + 2 * NC + t * 4);

    float sq = qv.x * qv.x + qv.y * qv.y + qv.z * qv.z + qv.w * qv.w;
    float sk = kv.x * kv.x + kv.y * kv.y + kv.z * kv.z + kv.w * kv.w;
#pragma unroll
    for (int m = 16; m > 0; m >>= 1) {
        sq += __shfl_xor_sync(0xffffffffu, sq, m);
        sk += __shfl_xor_sync(0xffffffffu, sk, m);
    }
    __shared__ float red[2][8];
    const int warp = t >> 5, lane = t & 31;
    if (lane == 0) { red[0][warp] = sq; red[1][warp] = sk; }
    __syncthreads();
    float sqt = 0.f, skt = 0.f;
#pragma unroll
    for (int w = 0; w < 8; w++) { sqt += red[0][w]; skt += red[1][w]; }

    const int h = t >> 4;
    const float qs = 0.125f / fmaxf(sqrtf(sqt), 1e-12f) / temp[h];  // fold 1/T
    const float ks = 0.125f / fmaxf(sqrtf(skt), 1e-12f);

    const int d = (t & 15) * 4;
    const size_t qoff = ((size_t)(b * NH + h) * NN + n) * ND + d;
    uint2 qo = make_uint2(h2_bits(qv.x * qs, qv.y * qs), h2_bits(qv.z * qs, qv.w * qs));
    uint2 ko = make_uint2(h2_bits(kv.x * ks, kv.y * ks), h2_bits(kv.z * ks, kv.w * ks));
    *(uint2*)&q[qoff] = qo;
    *(uint2*)&k[qoff] = ko;

    const size_t vbase = ((size_t)(b * NH + h) * ND + d) * NN + n;
    v[vbase]          = __float2half_rn(vv.x);
    v[vbase + NN]     = __float2half_rn(vv.y);
    v[vbase + 2 * NN] = __float2half_rn(vv.z);
    v[vbase + 3 * NN] = __float2half_rn(vv.w);
}

// =============================================================================
// Attention fp16. |logit|<=1/64 (before 1/T) -> no-max softmax.
// 8 warps x 16 q-rows; 64-key tiles double-buffered cp.async.
// SMEM (halves, stride 72): Qs[128] | Kst[2][64] | Vst[2][64] | Ps[128]
// =============================================================================
#define AH 72
#define QS_OFF  0
#define KST_OFF (128 * AH)
#define VST_OFF (KST_OFF + 2 * 64 * AH)
#define PS_OFF  (VST_OFF + 2 * 64 * AH)
#define ATTN_SMEM_BYTES ((PS_OFF + 128 * AH) * 2)   // 73728

__global__ __launch_bounds__(256) void attn_kernel(
    const __half* __restrict__ q, const __half* __restrict__ k,
    const __half* __restrict__ v, __half* __restrict__ att)
{
    extern __shared__ __align__(128) __half smemh[];
    const uint32_t sb = smem_u32(smemh);
    const uint32_t qs_base = sb + QS_OFF * 2;
    const uint32_t ps_base = sb + PS_OFF * 2;

    const int t = threadIdx.x;
    const int w = t >> 5, lane = t & 31;
    const int qtile = blockIdx.x;
    const int bh = blockIdx.y;
    const int b = bh >> 4, h = bh & 15;

    const __half* qg = q + ((size_t)bh * NN + qtile * 128) * ND;
    const __half* kg = k + (size_t)bh * NN * ND;
    const __half* vg = v + (size_t)bh * ND * NN;    // [d][n]

    const int a_row  = (lane & 7) + ((lane >> 3) & 1) * 8;
    const int a_colh = (lane >> 4) << 3;
    const int b_row  = (lane & 7) + ((lane >> 4) << 3);
    const int b_colh = ((lane >> 3) & 1) * 8;

    // ---- Q preload (1024 16B chunks, 4/thread; scale already folded) ----
#pragma unroll
    for (int i = 0; i < 4; i++) {
        int c = t + i * 256;
        int r = c >> 3, ch = c & 7;
        *(uint4*)(smemh + QS_OFF + r * AH + ch * 8) =
            *(const uint4*)(qg + (size_t)r * ND + ch * 8);
    }

    // producer: K 512 + V 512 chunks per stage, 4/thread
    auto issue = [&](int it) {
        const int stage = it & 1;
        const int kv0 = it * 64;
        const uint32_t kb = sb + (KST_OFF + stage * 64 * AH) * 2;
        const uint32_t vb = sb + (VST_OFF + stage * 64 * AH) * 2;
#pragma unroll
        for (int i = 0; i < 4; i++) {
            int c = t + i * 256;
            int mat = c >> 9;
            int r   = (c >> 3) & 63;
            int ch  = c & 7;
            if (!mat)
                cp_async16(kb + (uint32_t)(r * AH + ch * 8) * 2,
                           kg + (size_t)(kv0 + r) * ND + ch * 8);
            else
                cp_async16(vb + (uint32_t)(r * AH + ch * 8) * 2,
                           vg + (size_t)r * NN + kv0 + ch * 8);
        }
        CP_COMMIT();
    };

    float o[8][4];
#pragma unroll
    for (int ni = 0; ni < 8; ni++)
#pragma unroll
        for (int j = 0; j < 4; j++) o[ni][j] = 0.0f;
    float lsum0 = 0.0f, lsum1 = 0.0f;

    const int prow0 = w * 16 + (lane >> 2);
    const int pcol0 = (lane & 3) * 2;

    issue(0); issue(1);
    const int NITER = NN / 64;

    for (int it = 0; it < NITER; it++) {
        const int stage = it & 1;
        const uint32_t ks_base = sb + (KST_OFF + stage * 64 * AH) * 2;
        const uint32_t vs_base = sb + (VST_OFF + stage * 64 * AH) * 2;

        CP_WAIT(1);
        __syncthreads();

        // ---- S = Q K^T ----
        float s[8][4];
#pragma unroll
        for (int ni = 0; ni < 8; ni++)
#pragma unroll
            for (int j = 0; j < 4; j++) s[ni][j] = 0.0f;

#pragma unroll
        for (int ks = 0; ks < 4; ks++) {
            const int kc = ks * 16;
            uint32_t a[4];
            ldm_x4(a[0], a[1], a[2], a[3],
                   qs_base + ((w * 16 + a_row) * AH + kc + a_colh) * 2);
            uint32_t bb[4][4];
#pragma unroll
            for (int np = 0; np < 4; np++)
                ldm_x4(bb[np][0], bb[np][1], bb[np][2], bb[np][3],
                       ks_base + ((np * 16 + b_row) * AH + kc + b_colh) * 2);
#pragma unroll
            for (int ni = 0; ni < 8; ni++)
                mma_f16(s[ni], a, bb[ni >> 1][(ni & 1) * 2],
                        bb[ni >> 1][(ni & 1) * 2 + 1]);
        }

        // ---- P = exp(S), fp16 stash (warp-private rows) ----
#pragma unroll
        for (int ni = 0; ni < 8; ni++) {
            float e0 = __expf(s[ni][0]);
            float e1 = __expf(s[ni][1]);
            float e2 = __expf(s[ni][2]);
            float e3 = __expf(s[ni][3]);
            lsum0 += e0 + e1;
            lsum1 += e2 + e3;
            *(uint32_t*)(smemh + PS_OFF + prow0 * AH + ni * 8 + pcol0) = h2_bits(e0, e1);
            *(uint32_t*)(smemh + PS_OFF + (prow0 + 8) * AH + ni * 8 + pcol0) = h2_bits(e2, e3);
        }
        __syncwarp();

        // ---- O += P V ----
#pragma unroll
        for (int ks = 0; ks < 4; ks++) {
            const int kc = ks * 16;
            uint32_t a[4];
            ldm_x4(a[0], a[1], a[2], a[3],
                   ps_base + ((w * 16 + a_row) * AH + kc + a_colh) * 2);
            uint32_t bb[4][4];
#pragma unroll
            for (int np = 0; np < 4; np++)
                ldm_x4(bb[np][0], bb[np][1], bb[np][2], bb[np][3],
                       vs_base + ((np * 16 + b_row) * AH + kc + b_colh) * 2);
#pragma unroll
            for (int ni = 0; ni < 8; ni++)
                mma_f16(o[ni], a, bb[ni >> 1][(ni & 1) * 2],
                        bb[ni >> 1][(ni & 1) * 2 + 1]);
        }

        __syncthreads();
        if (it + 2 < NITER) issue(it + 2);
        else                CP_COMMIT();      // keep wait_group(1) exact in tail
    }

    lsum0 += __shfl_xor_sync(0xffffffffu, lsum0, 1);
    lsum0 += __shfl_xor_sync(0xffffffffu, lsum0, 2);
    lsum1 += __shfl_xor_sync(0xffffffffu, lsum1, 1);
    lsum1 += __shfl_xor_sync(0xffffffffu, lsum1, 2);
    const float inv0 = 1.0f / lsum0;
    const float inv1 = 1.0f / lsum1;

    const int grow0 = qtile * 128 + prow0;
#pragma unroll
    for (int ni = 0; ni < 8; ni++) {
        const int col = h * ND + ni * 8 + pcol0;
        *(uint32_t*)(att + (size_t)(b * NN + grow0) * NC + col) =
            h2_bits(o[ni][0] * inv0, o[ni][1] * inv0);
        *(uint32_t*)(att + (size_t)(b * NN + grow0 + 8) * NC + col) =
            h2_bits(o[ni][2] * inv1, o[ni][3] * inv1);
    }
}

// =============================================================================
// Launch
// =============================================================================
extern "C" void kernel_launch(void* const* d_in, const int* in_sizes, int n_in,
                              void* d_out, int out_size)
{
    (void)in_sizes; (void)n_in; (void)out_size;
    const float* x      = (const float*)d_in[0];
    const float* qkv_w  = (const float*)d_in[1];
    const float* temp   = (const float*)d_in[2];
    const float* proj_w = (const float*)d_in[3];
    const float* proj_b = (const float*)d_in[4];
    float* out = (float*)d_out;

    __half *p_xt, *p_wqkv, *p_wproj, *p_q, *p_k, *p_v, *p_att;
    float *p_qkv;
    cudaGetSymbolAddress((void**)&p_xt,    g_xt);
    cudaGetSymbolAddress((void**)&p_wqkv,  g_wqkv);
    cudaGetSymbolAddress((void**)&p_wproj, g_wproj);
    cudaGetSymbolAddress((void**)&p_qkv,   g_qkv);
    cudaGetSymbolAddress((void**)&p_q,     g_q);
    cudaGetSymbolAddress((void**)&p_k,     g_k);
    cudaGetSymbolAddress((void**)&p_v,     g_v);
    cudaGetSymbolAddress((void**)&p_att,   g_att);

    cudaFuncSetAttribute(gemm_f16<false>,
                         cudaFuncAttributeMaxDynamicSharedMemorySize, G_SMEM_TOTAL);
    cudaFuncSetAttribute(gemm_f16<true>,
                         cudaFuncAttributeMaxDynamicSharedMemorySize, G_SMEM_TOTAL);
    cudaFuncSetAttribute(attn_kernel,
                         cudaFuncAttributeMaxDynamicSharedMemorySize, ATTN_SMEM_BYTES);

    // 0) fp32 -> fp16 inputs
    cvt_f16_kernel<<<NTOK * NC / 8 / 256, 256>>>((const float4*)x, (uint4*)p_xt,
                                                 NTOK * NC / 8);
    cvt_f16_kernel<<<3 * NC * NC / 8 / 256, 256>>>((const float4*)qkv_w,
                                                   (uint4*)p_wqkv, 3 * NC * NC / 8);
    cvt_f16_kernel<<<NC * NC / 8 / 256, 256>>>((const float4*)proj_w,
                                               (uint4*)p_wproj, NC * NC / 8);

    // 1) QKV GEMM (fp16 in, fp32 out)
    gemm_f16<false><<<dim3(3 * NC / 128, NTOK / 128), 256, G_SMEM_TOTAL>>>(
        p_xt, p_wqkv, nullptr, p_qkv, NTOK, 3 * NC, NC);

    // 2) normalize + head split (q gets 0.125/T, k gets 0.125; v transposed)
    norm_split_kernel<<<NTOK, 256>>>(p_qkv, temp, p_q, p_k, p_v);

    // 3) attention
    attn_kernel<<<dim3(NN / 128, NB * NH), 256, ATTN_SMEM_BYTES>>>(
        p_q, p_k, p_v, p_att);

    // 4) projection (fp16 in, fp32 + bias out)
    gemm_f16<true><<<dim3(NC / 128, NTOK / 128), 256, G_SMEM_TOTAL>>>(
        p_att, p_wproj, proj_b, out, NTOK, NC, NC);
}

// round 7
// speedup vs baseline: 6.2015x; 1.0769x over previous
#include <cuda_runtime.h>
#include <cuda_fp16.h>
#include <math.h>
#include <stdint.h>

// B=2, N=2048, C=1024, H=16, D=64
#define NB 2
#define NN 2048
#define NC 1024
#define NH 16
#define ND 64
#define NTOK (NB * NN)

// ---------------- scratch ----------------
__device__ __half g_xt[NTOK * NC];          // x fp16
__device__ __half g_wqkv[3 * NC * NC];      // qkv_w fp16
__device__ __half g_wproj[NC * NC];         // proj_w fp16
__device__ float  g_qkv[NTOK * 3 * NC];     // GEMM1 out fp32
__device__ __half g_q[NTOK * NC];           // [bh][n][d] fp16, scaled 0.125/T[h]
__device__ __half g_k[NTOK * NC];           // [bh][n][d] fp16, scaled 0.125
__device__ __half g_v[NTOK * NC];           // [bh][d][n] fp16 TRANSPOSED
__device__ __half g_att[NTOK * NC];         // attention out fp16, token-major

// ---------------- PTX helpers ----------------
__device__ __forceinline__ uint32_t smem_u32(const void* p) {
    return (uint32_t)__cvta_generic_to_shared(p);
}
__device__ __forceinline__ void ldm_x4(uint32_t& r0, uint32_t& r1,
                                       uint32_t& r2, uint32_t& r3, uint32_t addr) {
    asm volatile("ldmatrix.sync.aligned.m8n8.x4.shared.b16 {%0,%1,%2,%3}, [%4];"
                 : "=r"(r0), "=r"(r1), "=r"(r2), "=r"(r3) : "r"(addr));
}
__device__ __forceinline__ void mma_f16(float* c, const uint32_t* a,
                                        uint32_t b0, uint32_t b1) {
    asm volatile(
        "mma.sync.aligned.m16n8k16.row.col.f32.f16.f16.f32 "
        "{%0,%1,%2,%3}, {%4,%5,%6,%7}, {%8,%9}, {%0,%1,%2,%3};"
        : "+f"(c[0]), "+f"(c[1]), "+f"(c[2]), "+f"(c[3])
        : "r"(a[0]), "r"(a[1]), "r"(a[2]), "r"(a[3]), "r"(b0), "r"(b1));
}
__device__ __forceinline__ void cp_async16(uint32_t saddr, const void* gptr) {
    asm volatile("cp.async.cg.shared.global [%0], [%1], 16;"
                 :: "r"(saddr), "l"(gptr));
}
#define CP_COMMIT() asm volatile("cp.async.commit_group;" ::: "memory")
#define CP_WAIT(n)  asm volatile("cp.async.wait_group %0;" :: "n"(n) : "memory")

__device__ __forceinline__ uint32_t h2_bits(float a, float b) {
    __half2 h = __floats2half2_rn(a, b);
    return *(uint32_t*)&h;
}

// =============================================================================
// fp32 -> fp16 conversion, 8 elems/thread
// =============================================================================
__global__ __launch_bounds__(256) void cvt_f16_kernel(
    const float4* __restrict__ src, uint4* __restrict__ dst, int n8)
{
    int i = blockIdx.x * 256 + threadIdx.x;
    if (i < n8) {
        float4 a = src[2 * i], b = src[2 * i + 1];
        uint4 o;
        o.x = h2_bits(a.x, a.y); o.y = h2_bits(a.z, a.w);
        o.z = h2_bits(b.x, b.y); o.w = h2_bits(b.z, b.w);
        dst[i] = o;
    }
}

// =============================================================================
// FP16 GEMM: C[M,N] = A[M,K]*B[N,K]^T (+bias), fp32 accum.
// CTA 128x128, 128 threads = 4 warps (2x2), warp tile 64x64 -> 8 LDSM : 64 HMMA
// per k-step. Ktile=32 halves, 4-stage cp.async ring, one sync/iter.
// SMEM rows: 40 halves (odd 16B atoms -> ldmatrix conflict-free).
// =============================================================================
#define GKH   32
#define GROWH 40
#define G_STAGE_BYTES (128 * GROWH * 2 * 2)    // A + B = 20480
#define G_SMEM_TOTAL  (4 * G_STAGE_BYTES)      // 81920

template <bool HAS_BIAS>
__global__ __launch_bounds__(128) void gemm_f16(
    const __half* __restrict__ A, const __half* __restrict__ Bm,
    const float* __restrict__ bias, float* __restrict__ C,
    int M, int Nc, int K)
{
    extern __shared__ __align__(128) char gsm[];
    const uint32_t sbase0 = smem_u32(gsm);

    const int t = threadIdx.x;
    const int w = t >> 5, lane = t & 31;
    const int wm = w >> 1, wn = w & 1;     // 2x2 warp grid, warp 64x64

    const __half* Ab = A  + (size_t)(blockIdx.y * 128) * K;
    const __half* Bb = Bm + (size_t)(blockIdx.x * 128) * K;

    const int a_row  = (lane & 7) + ((lane >> 3) & 1) * 8;
    const int a_colh = (lane >> 4) << 3;
    const int b_row  = (lane & 7) + ((lane >> 4) << 3);
    const int b_colh = ((lane >> 3) & 1) * 8;

    float acc[4][8][4];
#pragma unroll
    for (int mi = 0; mi < 4; mi++)
#pragma unroll
        for (int ni = 0; ni < 8; ni++)
#pragma unroll
            for (int j = 0; j < 4; j++) acc[mi][ni][j] = 0.0f;

    const int NT = K >> 5;

    // producer: 1024 16B chunks/stage, 8/thread (128 threads)
    auto issue = [&](int kt) {
        const uint32_t sb = sbase0 + (kt & 3) * G_STAGE_BYTES;
#pragma unroll
        for (int i = 0; i < 8; i++) {
            int c = t + i * 128;
            int mat = c >> 9;            // 0=A, 1=B
            int r   = (c >> 2) & 127;
            int q   = c & 3;
            const __half* g = (mat ? Bb : Ab) + (size_t)r * K + kt * GKH + q * 8;
            uint32_t sa = sb + (uint32_t)(mat * (128 * GROWH) + r * GROWH + q * 8) * 2;
            cp_async16(sa, g);
        }
        CP_COMMIT();
    };

    issue(0); issue(1); issue(2);

    for (int kt = 0; kt < NT; kt++) {
        const uint32_t as = sbase0 + (kt & 3) * G_STAGE_BYTES;
        const uint32_t bs = as + 128 * GROWH * 2;

        CP_WAIT(2);
        __syncthreads();

#pragma unroll
        for (int ks = 0; ks < 2; ks++) {
            const int kc = ks * 16;
            uint32_t a[4][4];
#pragma unroll
            for (int mi = 0; mi < 4; mi++)
                ldm_x4(a[mi][0], a[mi][1], a[mi][2], a[mi][3],
                       as + ((wm * 64 + mi * 16 + a_row) * GROWH + kc + a_colh) * 2);
            uint32_t b[4][4];
#pragma unroll
            for (int np = 0; np < 4; np++)
                ldm_x4(b[np][0], b[np][1], b[np][2], b[np][3],
                       bs + ((wn * 64 + np * 16 + b_row) * GROWH + kc + b_colh) * 2);
#pragma unroll
            for (int mi = 0; mi < 4; mi++)
#pragma unroll
                for (int ni = 0; ni < 8; ni++)
                    mma_f16(acc[mi][ni], a[mi],
                            b[ni >> 1][(ni & 1) * 2], b[ni >> 1][(ni & 1) * 2 + 1]);
        }

        if (kt + 3 < NT) issue(kt + 3);
        else             CP_COMMIT();      // keep wait_group(2) arithmetic exact
    }

    // epilogue (fp32)
    const int erow0 = blockIdx.y * 128 + wm * 64 + (lane >> 2);
    const int ecol0 = blockIdx.x * 128 + wn * 64 + (lane & 3) * 2;
#pragma unroll
    for (int mi = 0; mi < 4; mi++) {
#pragma unroll
        for (int ni = 0; ni < 8; ni++) {
            int r = erow0 + mi * 16;
            int c = ecol0 + ni * 8;
            float2 v01 = make_float2(acc[mi][ni][0], acc[mi][ni][1]);
            float2 v23 = make_float2(acc[mi][ni][2], acc[mi][ni][3]);
            if (HAS_BIAS) {
                float b0 = bias[c], b1 = bias[c + 1];
                v01.x += b0; v01.y += b1;
                v23.x += b0; v23.y += b1;
            }
            *(float2*)(C + (size_t)r * Nc + c)       = v01;
            *(float2*)(C + (size_t)(r + 8) * Nc + c) = v23;
        }
    }
}

// =============================================================================
// Normalize q,k over full C; q scaled 0.125/T[h], k scaled 0.125; fp16 out.
// v -> transposed [bh][d][n] fp16.
// =============================================================================
__global__ __launch_bounds__(256) void norm_split_kernel(
    const float* __restrict__ qkv, const float* __restrict__ temp,
    __half* __restrict__ q, __half* __restrict__ k, __half* __restrict__ v)
{
    const int tok = blockIdx.x;
    const int b = tok >> 11;
    const int n = tok & 2047;
    const float* row = qkv + (size_t)tok * (3 * NC);
    const int t = threadIdx.x;

    float4 qv = *(const float4*)(row + t * 4);
    float4 kv = *(const float4*)(row + NC + t * 4);
    float4 vv = *(const float4*)(row + 2 * NC + t * 4);

    float sq = qv.x * qv.x + qv.y * qv.y + qv.z * qv.z + qv.w * qv.w;
    float sk = kv.x * kv.x + kv.y * kv.y + kv.z * kv.z + kv.w * kv.w;
#pragma unroll
    for (int m = 16; m > 0; m >>= 1) {
        sq += __shfl_xor_sync(0xffffffffu, sq, m);
        sk += __shfl_xor_sync(0xffffffffu, sk, m);
    }
    __shared__ float red[2][8];
    const int warp = t >> 5, lane = t & 31;
    if (lane == 0) { red[0][warp] = sq; red[1][warp] = sk; }
    __syncthreads();
    float sqt = 0.f, skt = 0.f;
#pragma unroll
    for (int w = 0; w < 8; w++) { sqt += red[0][w]; skt += red[1][w]; }

    const int h = t >> 4;
    const float qs = 0.125f / fmaxf(sqrtf(sqt), 1e-12f) / temp[h];
    const float ks = 0.125f / fmaxf(sqrtf(skt), 1e-12f);

    const int d = (t & 15) * 4;
    const size_t qoff = ((size_t)(b * NH + h) * NN + n) * ND + d;
    uint2 qo = make_uint2(h2_bits(qv.x * qs, qv.y * qs), h2_bits(qv.z * qs, qv.w * qs));
    uint2 ko = make_uint2(h2_bits(kv.x * ks, kv.y * ks), h2_bits(kv.z * ks, kv.w * ks));
    *(uint2*)&q[qoff] = qo;
    *(uint2*)&k[qoff] = ko;

    const size_t vbase = ((size_t)(b * NH + h) * ND + d) * NN + n;
    v[vbase]          = __float2half_rn(vv.x);
    v[vbase + NN]     = __float2half_rn(vv.y);
    v[vbase + 2 * NN] = __float2half_rn(vv.z);
    v[vbase + 3 * NN] = __float2half_rn(vv.w);
}

// =============================================================================
// Attention fp16, P KEPT IN REGISTERS (S C-fragment == PV A-fragment layout).
// 8 warps x 16 q-rows; 64-key tiles double-buffered cp.async.
// SMEM (halves, stride 72): Qs[128] | Kst[2][64] | Vst[2][64]   (55296 B)
// =============================================================================
#define AH 72
#define QS_OFF  0
#define KST_OFF (128 * AH)
#define VST_OFF (KST_OFF + 2 * 64 * AH)
#define ATTN_SMEM_BYTES ((VST_OFF + 2 * 64 * AH) * 2)   // 55296

__global__ __launch_bounds__(256) void attn_kernel(
    const __half* __restrict__ q, const __half* __restrict__ k,
    const __half* __restrict__ v, __half* __restrict__ att)
{
    extern __shared__ __align__(128) __half smemh[];
    const uint32_t sb = smem_u32(smemh);
    const uint32_t qs_base = sb + QS_OFF * 2;

    const int t = threadIdx.x;
    const int w = t >> 5, lane = t & 31;
    const int qtile = blockIdx.x;
    const int bh = blockIdx.y;
    const int b = bh >> 4, h = bh & 15;

    const __half* qg = q + ((size_t)bh * NN + qtile * 128) * ND;
    const __half* kg = k + (size_t)bh * NN * ND;
    const __half* vg = v + (size_t)bh * ND * NN;    // [d][n]

    const int a_row  = (lane & 7) + ((lane >> 3) & 1) * 8;
    const int a_colh = (lane >> 4) << 3;
    const int b_row  = (lane & 7) + ((lane >> 4) << 3);
    const int b_colh = ((lane >> 3) & 1) * 8;

    // ---- Q preload ----
#pragma unroll
    for (int i = 0; i < 4; i++) {
        int c = t + i * 256;
        int r = c >> 3, ch = c & 7;
        *(uint4*)(smemh + QS_OFF + r * AH + ch * 8) =
            *(const uint4*)(qg + (size_t)r * ND + ch * 8);
    }

    // producer: K 512 + V 512 chunks per stage, 4/thread
    auto issue = [&](int it) {
        const int stage = it & 1;
        const int kv0 = it * 64;
        const uint32_t kb = sb + (KST_OFF + stage * 64 * AH) * 2;
        const uint32_t vb = sb + (VST_OFF + stage * 64 * AH) * 2;
#pragma unroll
        for (int i = 0; i < 4; i++) {
            int c = t + i * 256;
            int mat = c >> 9;
            int r   = (c >> 3) & 63;
            int ch  = c & 7;
            if (!mat)
                cp_async16(kb + (uint32_t)(r * AH + ch * 8) * 2,
                           kg + (size_t)(kv0 + r) * ND + ch * 8);
            else
                cp_async16(vb + (uint32_t)(r * AH + ch * 8) * 2,
                           vg + (size_t)r * NN + kv0 + ch * 8);
        }
        CP_COMMIT();
    };

    float o[8][4];
#pragma unroll
    for (int ni = 0; ni < 8; ni++)
#pragma unroll
        for (int j = 0; j < 4; j++) o[ni][j] = 0.0f;
    float lsum0 = 0.0f, lsum1 = 0.0f;

    issue(0); issue(1);
    const int NITER = NN / 64;

    for (int it = 0; it < NITER; it++) {
        const int stage = it & 1;
        const uint32_t ks_base = sb + (KST_OFF + stage * 64 * AH) * 2;
        const uint32_t vs_base = sb + (VST_OFF + stage * 64 * AH) * 2;

        CP_WAIT(1);
        __syncthreads();

        // ---- S = Q K^T (warp: 16 rows x 64 keys) ----
        float s[8][4];
#pragma unroll
        for (int ni = 0; ni < 8; ni++)
#pragma unroll
            for (int j = 0; j < 4; j++) s[ni][j] = 0.0f;

#pragma unroll
        for (int ks = 0; ks < 4; ks++) {
            const int kc = ks * 16;
            uint32_t a[4];
            ldm_x4(a[0], a[1], a[2], a[3],
                   qs_base + ((w * 16 + a_row) * AH + kc + a_colh) * 2);
            uint32_t bb[4][4];
#pragma unroll
            for (int np = 0; np < 4; np++)
                ldm_x4(bb[np][0], bb[np][1], bb[np][2], bb[np][3],
                       ks_base + ((np * 16 + b_row) * AH + kc + b_colh) * 2);
#pragma unroll
            for (int ni = 0; ni < 8; ni++)
                mma_f16(s[ni], a, bb[ni >> 1][(ni & 1) * 2],
                        bb[ni >> 1][(ni & 1) * 2 + 1]);
        }

        // ---- fused exp + PV: P lives in registers as A-fragments ----
        // S C-frag (c0,c1 @ row g; c2,c3 @ row g+8) maps to PV A-frag:
        // key-block kk (16 keys): a = { pack(s[2kk][0,1]),  pack(s[2kk][2,3]),
        //                              pack(s[2kk+1][0,1]), pack(s[2kk+1][2,3]) }
#pragma unroll
        for (int kk = 0; kk < 4; kk++) {
            float ea0 = __expf(s[2 * kk][0]), ea1 = __expf(s[2 * kk][1]);
            float ea2 = __expf(s[2 * kk][2]), ea3 = __expf(s[2 * kk][3]);
            float eb0 = __expf(s[2 * kk + 1][0]), eb1 = __expf(s[2 * kk + 1][1]);
            float eb2 = __expf(s[2 * kk + 1][2]), eb3 = __expf(s[2 * kk + 1][3]);
            lsum0 += (ea0 + ea1) + (eb0 + eb1);
            lsum1 += (ea2 + ea3) + (eb2 + eb3);
            uint32_t pa[4];
            pa[0] = h2_bits(ea0, ea1);
            pa[1] = h2_bits(ea2, ea3);
            pa[2] = h2_bits(eb0, eb1);
            pa[3] = h2_bits(eb2, eb3);

            const int kc = kk * 16;      // key offset within tile
            uint32_t bb[4][4];
#pragma unroll
            for (int np = 0; np < 4; np++)
                ldm_x4(bb[np][0], bb[np][1], bb[np][2], bb[np][3],
                       vs_base + ((np * 16 + b_row) * AH + kc + b_colh) * 2);
#pragma unroll
            for (int ni = 0; ni < 8; ni++)
                mma_f16(o[ni], pa, bb[ni >> 1][(ni & 1) * 2],
                        bb[ni >> 1][(ni & 1) * 2 + 1]);
        }

        __syncthreads();
        if (it + 2 < NITER) issue(it + 2);
        else                CP_COMMIT();
    }

    lsum0 += __shfl_xor_sync(0xffffffffu, lsum0, 1);
    lsum0 += __shfl_xor_sync(0xffffffffu, lsum0, 2);
    lsum1 += __shfl_xor_sync(0xffffffffu, lsum1, 1);
    lsum1 += __shfl_xor_sync(0xffffffffu, lsum1, 2);
    const float inv0 = 1.0f / lsum0;
    const float inv1 = 1.0f / lsum1;

    const int prow0 = w * 16 + (lane >> 2);
    const int pcol0 = (lane & 3) * 2;
    const int grow0 = qtile * 128 + prow0;
#pragma unroll
    for (int ni = 0; ni < 8; ni++) {
        const int col = h * ND + ni * 8 + pcol0;
        *(uint32_t*)(att + (size_t)(b * NN + grow0) * NC + col) =
            h2_bits(o[ni][0] * inv0, o[ni][1] * inv0);
        *(uint32_t*)(att + (size_t)(b * NN + grow0 + 8) * NC + col) =
            h2_bits(o[ni][2] * inv1, o[ni][3] * inv1);
    }
}

// =============================================================================
// Launch
// =============================================================================
extern "C" void kernel_launch(void* const* d_in, const int* in_sizes, int n_in,
                              void* d_out, int out_size)
{
    (void)in_sizes; (void)n_in; (void)out_size;
    const float* x      = (const float*)d_in[0];
    const float* qkv_w  = (const float*)d_in[1];
    const float* temp   = (const float*)d_in[2];
    const float* proj_w = (const float*)d_in[3];
    const float* proj_b = (const float*)d_in[4];
    float* out = (float*)d_out;

    __half *p_xt, *p_wqkv, *p_wproj, *p_q, *p_k, *p_v, *p_att;
    float *p_qkv;
    cudaGetSymbolAddress((void**)&p_xt,    g_xt);
    cudaGetSymbolAddress((void**)&p_wqkv,  g_wqkv);
    cudaGetSymbolAddress((void**)&p_wproj, g_wproj);
    cudaGetSymbolAddress((void**)&p_qkv,   g_qkv);
    cudaGetSymbolAddress((void**)&p_q,     g_q);
    cudaGetSymbolAddress((void**)&p_k,     g_k);
    cudaGetSymbolAddress((void**)&p_v,     g_v);
    cudaGetSymbolAddress((void**)&p_att,   g_att);

    cudaFuncSetAttribute(gemm_f16<false>,
                         cudaFuncAttributeMaxDynamicSharedMemorySize, G_SMEM_TOTAL);
    cudaFuncSetAttribute(gemm_f16<true>,
                         cudaFuncAttributeMaxDynamicSharedMemorySize, G_SMEM_TOTAL);
    cudaFuncSetAttribute(attn_kernel,
                         cudaFuncAttributeMaxDynamicSharedMemorySize, ATTN_SMEM_BYTES);

    // 0) fp32 -> fp16 inputs
    cvt_f16_kernel<<<NTOK * NC / 8 / 256, 256>>>((const float4*)x, (uint4*)p_xt,
                                                 NTOK * NC / 8);
    cvt_f16_kernel<<<3 * NC * NC / 8 / 256, 256>>>((const float4*)qkv_w,
                                                   (uint4*)p_wqkv, 3 * NC * NC / 8);
    cvt_f16_kernel<<<NC * NC / 8 / 256, 256>>>((const float4*)proj_w,
                                               (uint4*)p_wproj, NC * NC / 8);

    // 1) QKV GEMM (fp16 in, fp32 out), 128-thread CTAs
    gemm_f16<false><<<dim3(3 * NC / 128, NTOK / 128), 128, G_SMEM_TOTAL>>>(
        p_xt, p_wqkv, nullptr, p_qkv, NTOK, 3 * NC, NC);

    // 2) normalize + head split
    norm_split_kernel<<<NTOK, 256>>>(p_qkv, temp, p_q, p_k, p_v);

    // 3) attention (P in registers)
    attn_kernel<<<dim3(NN / 128, NB * NH), 256, ATTN_SMEM_BYTES>>>(
        p_q, p_k, p_v, p_att);

    // 4) projection
    gemm_f16<true><<<dim3(NC / 128, NTOK / 128), 128, G_SMEM_TOTAL>>>(
        p_att, p_wproj, proj_b, out, NTOK, NC, NC);
}